// round 1
// baseline (speedup 1.0000x reference)
#include <cuda_runtime.h>
#include <cuda_bf16.h>
#include <cstdint>

// Problem constants (fixed shapes)
#define NN 8192
#define FIN 512
#define FF 64
#define SPLIT 4
#define JPB (NN / SPLIT)   // 2048 j per split-block
#define BM 64              // rows per block (K4)
#define BJ 32              // j chunk (K4)
#define TH4 128            // threads (K4)
#define WPAD 66            // padded w_s row stride (floats)

typedef unsigned long long ull;

// -------------------- device scratch --------------------
__device__ float g_Wh[NN * FF];
__device__ float g_e1[NN];
__device__ float g_e2[NN];
__device__ float g_E[NN];
__device__ float g_F[NN];
__device__ float g_A[NN];
__device__ float g_B[NN];
__device__ float g_blockmax[32];
__device__ float g_num[SPLIT][NN * FF];
__device__ float g_den[SPLIT][NN];

// -------------------- f32x2 helpers --------------------
__device__ __forceinline__ ull f2_fma(ull a, ull b, ull c) {
    ull d;
    asm("fma.rn.f32x2 %0, %1, %2, %3;" : "=l"(d) : "l"(a), "l"(b), "l"(c));
    return d;
}
__device__ __forceinline__ ull f2_dup(float x) {
    ull d;
    asm("mov.b64 %0, {%1, %1};" : "=l"(d) : "f"(x));
    return d;
}
__device__ __forceinline__ float f2_lo(ull v) { return __uint_as_float((unsigned)v); }
__device__ __forceinline__ float f2_hi(ull v) { return __uint_as_float((unsigned)(v >> 32)); }

// -------------------- K1: Wh = h @ W --------------------
// grid 128 blocks (64 rows each), 256 threads, micro 4x4, k-tile 32
__global__ __launch_bounds__(256) void k1_gemm(const float* __restrict__ h,
                                               const float* __restrict__ W) {
    __shared__ __align__(16) float As[32 * 66];  // [k][row], padded
    __shared__ __align__(16) float Bs[32 * 64];  // [k][col]
    int t = threadIdx.x;
    int r0 = blockIdx.x * 64;
    int tx = t & 15;   // col group: cols 4*tx..4*tx+3
    int ty = t >> 4;   // row group: rows 4*ty..4*ty+3
    float acc[4][4];
#pragma unroll
    for (int i = 0; i < 4; i++)
#pragma unroll
        for (int j = 0; j < 4; j++) acc[i][j] = 0.f;

    for (int k0 = 0; k0 < FIN; k0 += 32) {
        __syncthreads();
        // load h tile 64x32 (transposed store)
#pragma unroll
        for (int q = 0; q < 8; q++) {
            int idx = t + 256 * q;           // 0..2047
            int kk = idx & 31, i = idx >> 5;
            As[kk * 66 + i] = h[(r0 + i) * FIN + k0 + kk];
        }
        // load W tile 32x64
#pragma unroll
        for (int q = 0; q < 8; q++) {
            int idx = t + 256 * q;
            int c = idx & 63, kk = idx >> 6;
            Bs[kk * 64 + c] = W[(k0 + kk) * FF + c];
        }
        __syncthreads();
#pragma unroll
        for (int kk = 0; kk < 32; kk++) {
            float2 a01 = *(const float2*)&As[kk * 66 + 4 * ty];
            float2 a23 = *(const float2*)&As[kk * 66 + 4 * ty + 2];
            float4 b = *(const float4*)&Bs[kk * 64 + 4 * tx];
            float av[4] = {a01.x, a01.y, a23.x, a23.y};
            float bv[4] = {b.x, b.y, b.z, b.w};
#pragma unroll
            for (int i = 0; i < 4; i++)
#pragma unroll
                for (int j = 0; j < 4; j++) acc[i][j] = fmaf(av[i], bv[j], acc[i][j]);
        }
    }
#pragma unroll
    for (int i = 0; i < 4; i++) {
        float4 v = make_float4(acc[i][0], acc[i][1], acc[i][2], acc[i][3]);
        *(float4*)&g_Wh[(r0 + 4 * ty + i) * FF + 4 * tx] = v;
    }
}

// -------------------- K2: e1, e2, per-block max(e2) --------------------
// grid 32 blocks x 256 threads, one thread per row
__global__ __launch_bounds__(256) void k2_e(const float* __restrict__ a) {
    __shared__ float red[256];
    int t = threadIdx.x;
    int i = blockIdx.x * 256 + t;
    const float4* wh = (const float4*)&g_Wh[i * FF];
    float e1 = 0.f, e2 = 0.f;
#pragma unroll
    for (int q = 0; q < 16; q++) {
        float4 v = wh[q];
        float4 a1 = *(const float4*)&a[q * 4];
        float4 a2 = *(const float4*)&a[FF + q * 4];
        e1 += v.x * a1.x + v.y * a1.y + v.z * a1.z + v.w * a1.w;
        e2 += v.x * a2.x + v.y * a2.y + v.z * a2.z + v.w * a2.w;
    }
    g_e1[i] = e1;
    g_e2[i] = e2;
    red[t] = e2;
    __syncthreads();
    for (int s = 128; s > 0; s >>= 1) {
        if (t < s) red[t] = fmaxf(red[t], red[t + s]);
        __syncthreads();
    }
    if (t == 0) g_blockmax[blockIdx.x] = red[0];
}

// -------------------- K3: E, F, A, B --------------------
__global__ __launch_bounds__(256) void k3_ef() {
    int i = blockIdx.x * 256 + threadIdx.x;
    float m = -1e30f;
#pragma unroll
    for (int b = 0; b < 32; b++) m = fmaxf(m, g_blockmax[b]);
    float e1 = g_e1[i], e2 = g_e2[i];
    float x = e1 + m;
    float C = (x > 0.f) ? x : 0.2f * x;     // lrelu upper bound of row max
    g_A[i] = expf(e1 - C);
    g_B[i] = expf(0.2f * e1 - C);
    g_E[i] = expf(e2);
    g_F[i] = expf(0.2f * e2);
}

// -------------------- K4: fused masked-attention GEMM --------------------
// grid = 128 rowblocks * SPLIT, 128 threads.
// Each block: rows r0..r0+63, j in [bs*2048, bs*2048+2048).
__global__ __launch_bounds__(TH4) void k4_main(const int* __restrict__ adj) {
    __shared__ __align__(16) float w_s[BJ * WPAD];  // [j][row], padded stride 66
    __shared__ __align__(16) float wh_s[BJ * FF];   // [j][f]
    __shared__ float e1s[BM], As[BM], Bs[BM];

    int t = threadIdx.x;
    int bi = blockIdx.x & 127;
    int bs = blockIdx.x >> 7;
    int r0 = bi * BM;
    int j0base = bs * JPB;

    if (t < BM) {
        e1s[t] = g_e1[r0 + t];
        As[t] = g_A[r0 + t];
        Bs[t] = g_B[r0 + t];
    }

    // gen-phase mapping
    int jl = t & 31;   // lane = j within chunk
    int ig = t >> 5;   // warp id = row offset (rows ig + 4k)
    // ffma-phase mapping
    int tr = t & 7;    // rows 8*tr .. 8*tr+7
    int tc = t >> 3;   // cols 4*tc .. 4*tc+3

    ull acc[4][4];     // [rowpair p][col c]; pair = rows (8tr+2p, 8tr+2p+1)
#pragma unroll
    for (int p = 0; p < 4; p++)
#pragma unroll
        for (int c = 0; c < 4; c++) acc[p][c] = 0ULL;
    float den[16];
#pragma unroll
    for (int k = 0; k < 16; k++) den[k] = 0.f;

    for (int jc = 0; jc < JPB; jc += BJ) {
        int j0 = j0base + jc;
        float e2v = g_e2[j0 + jl];
        float Ev = g_E[j0 + jl];
        float Fv = g_F[j0 + jl];
        __syncthreads();  // previous chunk's FFMA done with smem
        // stage Wh chunk 32x64
#pragma unroll
        for (int q = 0; q < 4; q++) {
            int idx = t + TH4 * q;        // 0..511
            int jj = idx >> 4;
            int f4 = idx & 15;
            float4 v = *(const float4*)&g_Wh[(j0 + jj) * FF + f4 * 4];
            *(float4*)&wh_s[jj * FF + f4 * 4] = v;
        }
        // generate w
#pragma unroll
        for (int k = 0; k < 16; k++) {
            int i = ig + 4 * k;
            int av = adj[(r0 + i) * NN + (j0 + jl)];
            float x = e1s[i] + e2v;
            float w = (x > 0.f) ? As[i] * Ev : Bs[i] * Fv;
            w = (av > 0) ? w : 0.f;
            w_s[jl * WPAD + i] = w;
            den[k] += w;
        }
        __syncthreads();
        // FFMA phase
#pragma unroll 8
        for (int j = 0; j < BJ; j++) {
            ull wp[4];
#pragma unroll
            for (int p = 0; p < 4; p++)
                wp[p] = *(const ull*)&w_s[j * WPAD + 8 * tr + 2 * p];
            float4 wh4 = *(const float4*)&wh_s[j * FF + 4 * tc];
            ull d0 = f2_dup(wh4.x), d1 = f2_dup(wh4.y);
            ull d2 = f2_dup(wh4.z), d3 = f2_dup(wh4.w);
#pragma unroll
            for (int p = 0; p < 4; p++) {
                acc[p][0] = f2_fma(wp[p], d0, acc[p][0]);
                acc[p][1] = f2_fma(wp[p], d1, acc[p][1]);
                acc[p][2] = f2_fma(wp[p], d2, acc[p][2]);
                acc[p][3] = f2_fma(wp[p], d3, acc[p][3]);
            }
        }
    }

    // write numerator partials
#pragma unroll
    for (int p = 0; p < 4; p++) {
        int row = r0 + 8 * tr + 2 * p;
#pragma unroll
        for (int c = 0; c < 4; c++) {
            int col = 4 * tc + c;
            g_num[bs][row * FF + col] = f2_lo(acc[p][c]);
            g_num[bs][(row + 1) * FF + col] = f2_hi(acc[p][c]);
        }
    }
    // denominator: warp reduce over lanes (jl), lane 0 writes
#pragma unroll
    for (int k = 0; k < 16; k++) {
        float v = den[k];
#pragma unroll
        for (int o = 16; o > 0; o >>= 1) v += __shfl_xor_sync(0xffffffffu, v, o);
        if (jl == 0) g_den[bs][r0 + ig + 4 * k] = v;
    }
}

// -------------------- K5: reduce splits, normalize, ELU --------------------
__global__ __launch_bounds__(256) void k5_out(float* __restrict__ out) {
    int idx = blockIdx.x * 256 + threadIdx.x;  // 0..524287
    int i = idx >> 6;
    float num = g_num[0][idx] + g_num[1][idx] + g_num[2][idx] + g_num[3][idx];
    float den = g_den[0][i] + g_den[1][i] + g_den[2][i] + g_den[3][i];
    den = fmaxf(den, 1e-30f);
    float v = num / den;
    out[idx] = (v > 0.f) ? v : expm1f(v);
}

// -------------------- launch --------------------
extern "C" void kernel_launch(void* const* d_in, const int* in_sizes, int n_in,
                              void* d_out, int out_size) {
    const float* h = (const float*)d_in[0];
    const int* adj = (const int*)d_in[1];
    const float* W = (const float*)d_in[2];
    const float* a = (const float*)d_in[3];
    float* out = (float*)d_out;

    k1_gemm<<<NN / 64, 256>>>(h, W);
    k2_e<<<NN / 256, 256>>>(a);
    k3_ef<<<NN / 256, 256>>>();
    k4_main<<<(NN / BM) * SPLIT, TH4>>>(adj);
    k5_out<<<(NN * FF) / 256, 256>>>(out);
}

// round 2
// speedup vs baseline: 1.3939x; 1.3939x over previous
#include <cuda_runtime.h>
#include <cuda_bf16.h>
#include <cstdint>

// Problem constants (fixed shapes)
#define NN 8192
#define FIN 512
#define FF 64
#define SPLIT 6
#define BM 64              // rows per block (K4)
#define BJ 32              // j chunk (K4)
#define TH4 128            // threads (K4)
#define WPAD 66            // padded w_s row stride (floats)
#define NCH_TOT (NN / BJ)  // 256 chunks total

typedef unsigned long long ull;

// -------------------- device scratch --------------------
__device__ float g_Wh[NN * FF];
__device__ float g_e1[NN];
__device__ float g_e2[NN];
__device__ float g_E[NN];
__device__ float g_F[NN];
__device__ float g_A[NN];
__device__ float g_B[NN];
__device__ float g_blockmax[32];
__device__ float g_num[SPLIT][NN * FF];
__device__ float g_den[SPLIT][NN];

// -------------------- f32x2 helpers --------------------
__device__ __forceinline__ ull f2_fma(ull a, ull b, ull c) {
    ull d;
    asm("fma.rn.f32x2 %0, %1, %2, %3;" : "=l"(d) : "l"(a), "l"(b), "l"(c));
    return d;
}
__device__ __forceinline__ ull f2_dup(float x) {
    ull d;
    asm("mov.b64 %0, {%1, %1};" : "=l"(d) : "f"(x));
    return d;
}
__device__ __forceinline__ float f2_lo(ull v) { return __uint_as_float((unsigned)v); }
__device__ __forceinline__ float f2_hi(ull v) { return __uint_as_float((unsigned)(v >> 32)); }

__device__ __forceinline__ void cp16(void* sdst, const void* gsrc) {
    unsigned s = (unsigned)__cvta_generic_to_shared(sdst);
    asm volatile("cp.async.cg.shared.global [%0], [%1], 16;\n" :: "r"(s), "l"(gsrc));
}
#define CP_COMMIT() asm volatile("cp.async.commit_group;\n" ::: "memory")
#define CP_WAIT0()  asm volatile("cp.async.wait_group 0;\n" ::: "memory")

// -------------------- K1: Wh = h @ W --------------------
__global__ __launch_bounds__(256) void k1_gemm(const float* __restrict__ h,
                                               const float* __restrict__ W) {
    __shared__ __align__(16) float As[32 * 66];
    __shared__ __align__(16) float Bs[32 * 64];
    int t = threadIdx.x;
    int r0 = blockIdx.x * 64;
    int tx = t & 15;
    int ty = t >> 4;
    float acc[4][4];
#pragma unroll
    for (int i = 0; i < 4; i++)
#pragma unroll
        for (int j = 0; j < 4; j++) acc[i][j] = 0.f;

    for (int k0 = 0; k0 < FIN; k0 += 32) {
        __syncthreads();
#pragma unroll
        for (int q = 0; q < 8; q++) {
            int idx = t + 256 * q;
            int kk = idx & 31, i = idx >> 5;
            As[kk * 66 + i] = h[(r0 + i) * FIN + k0 + kk];
        }
#pragma unroll
        for (int q = 0; q < 8; q++) {
            int idx = t + 256 * q;
            int c = idx & 63, kk = idx >> 6;
            Bs[kk * 64 + c] = W[(k0 + kk) * FF + c];
        }
        __syncthreads();
#pragma unroll
        for (int kk = 0; kk < 32; kk++) {
            float2 a01 = *(const float2*)&As[kk * 66 + 4 * ty];
            float2 a23 = *(const float2*)&As[kk * 66 + 4 * ty + 2];
            float4 b = *(const float4*)&Bs[kk * 64 + 4 * tx];
            float av[4] = {a01.x, a01.y, a23.x, a23.y};
            float bv[4] = {b.x, b.y, b.z, b.w};
#pragma unroll
            for (int i = 0; i < 4; i++)
#pragma unroll
                for (int j = 0; j < 4; j++) acc[i][j] = fmaf(av[i], bv[j], acc[i][j]);
        }
    }
#pragma unroll
    for (int i = 0; i < 4; i++) {
        float4 v = make_float4(acc[i][0], acc[i][1], acc[i][2], acc[i][3]);
        *(float4*)&g_Wh[(r0 + 4 * ty + i) * FF + 4 * tx] = v;
    }
}

// -------------------- K2: e1, e2, per-block max(e2) --------------------
__global__ __launch_bounds__(256) void k2_e(const float* __restrict__ a) {
    __shared__ float red[256];
    int t = threadIdx.x;
    int i = blockIdx.x * 256 + t;
    const float4* wh = (const float4*)&g_Wh[i * FF];
    float e1 = 0.f, e2 = 0.f;
#pragma unroll
    for (int q = 0; q < 16; q++) {
        float4 v = wh[q];
        float4 a1 = *(const float4*)&a[q * 4];
        float4 a2 = *(const float4*)&a[FF + q * 4];
        e1 += v.x * a1.x + v.y * a1.y + v.z * a1.z + v.w * a1.w;
        e2 += v.x * a2.x + v.y * a2.y + v.z * a2.z + v.w * a2.w;
    }
    g_e1[i] = e1;
    g_e2[i] = e2;
    red[t] = e2;
    __syncthreads();
    for (int s = 128; s > 0; s >>= 1) {
        if (t < s) red[t] = fmaxf(red[t], red[t + s]);
        __syncthreads();
    }
    if (t == 0) g_blockmax[blockIdx.x] = red[0];
}

// -------------------- K3: E, F, A, B --------------------
__global__ __launch_bounds__(256) void k3_ef() {
    int i = blockIdx.x * 256 + threadIdx.x;
    float m = -1e30f;
#pragma unroll
    for (int b = 0; b < 32; b++) m = fmaxf(m, g_blockmax[b]);
    float e1 = g_e1[i], e2 = g_e2[i];
    float x = e1 + m;
    float C = (x > 0.f) ? x : 0.2f * x;     // lrelu upper bound of row max
    g_A[i] = expf(e1 - C);
    g_B[i] = expf(0.2f * e1 - C);
    g_E[i] = expf(e2);
    g_F[i] = expf(0.2f * e2);
}

// -------------------- K4: fused masked-attention GEMM --------------------
// grid = 128 rowblocks * SPLIT = 768 CTAs (one resident wave at 6 CTAs/SM).
// Split bs handles chunks [cstart, cstart+ccount): 43,43,43,43,42,42.
__global__ __launch_bounds__(TH4, 6) void k4_main(const int* __restrict__ adj) {
    __shared__ __align__(16) float w_s[BJ * WPAD];   // [j][row], padded
    __shared__ __align__(16) float wh_s[BJ * FF];    // [j][f]
    __shared__ __align__(16) int adjs[2][BM * BJ];   // double-buffered adj chunk
    __shared__ float e1s[BM], As[BM], Bs[BM];

    int t = threadIdx.x;
    int bi = blockIdx.x & 127;
    int bs = blockIdx.x >> 7;          // 0..5
    int r0 = bi * BM;
    int cstart = bs * 43 - ((bs > 4) ? (bs - 4) : 0);
    int ccount = (bs < 4) ? 43 : 42;
    int cend = cstart + ccount;

    if (t < BM) {
        e1s[t] = g_e1[r0 + t];
        As[t] = g_A[r0 + t];
        Bs[t] = g_B[r0 + t];
    }

    // gen-phase mapping
    int jl = t & 31;   // j within chunk
    int ig = t >> 5;   // row offset (rows ig + 4k)
    // ffma-phase mapping
    int tr = t & 7;    // rows 8*tr .. 8*tr+7
    int tc = t >> 3;   // cols 4*tc .. 4*tc+3

    ull acc[4][4];
#pragma unroll
    for (int p = 0; p < 4; p++)
#pragma unroll
        for (int c = 0; c < 4; c++) acc[p][c] = 0ULL;
    float den[16];
#pragma unroll
    for (int k = 0; k < 16; k++) den[k] = 0.f;

    // prologue: prefetch first chunk's adj
    {
        int j0 = cstart * BJ;
#pragma unroll
        for (int q = 0; q < 4; q++) {
            int e4 = t + TH4 * q;          // 0..511 (int4 units)
            int i = e4 >> 3;
            int j4 = (e4 & 7) * 4;
            cp16(&adjs[cstart & 1][i * BJ + j4], &adj[(r0 + i) * NN + j0 + j4]);
        }
        CP_COMMIT();
    }

    for (int c = cstart; c < cend; c++) {
        int j0 = c * BJ;
        int cur = c & 1;
        float e2v = g_e2[j0 + jl];
        float Ev = g_E[j0 + jl];
        float Fv = g_F[j0 + jl];

        CP_WAIT0();          // adj chunk c landed (per-thread)
        __syncthreads();     // all threads waited -> adjs[cur] visible; prev FFMA done

        // stage Wh chunk 32x64
#pragma unroll
        for (int q = 0; q < 4; q++) {
            int idx = t + TH4 * q;
            int jj = idx >> 4;
            int f4 = idx & 15;
            float4 v = *(const float4*)&g_Wh[(j0 + jj) * FF + f4 * 4];
            *(float4*)&wh_s[jj * FF + f4 * 4] = v;
        }
        // prefetch next chunk's adj (hidden under this chunk's FFMA)
        if (c + 1 < cend) {
            int j0n = (c + 1) * BJ;
#pragma unroll
            for (int q = 0; q < 4; q++) {
                int e4 = t + TH4 * q;
                int i = e4 >> 3;
                int j4 = (e4 & 7) * 4;
                cp16(&adjs[cur ^ 1][i * BJ + j4], &adj[(r0 + i) * NN + j0n + j4]);
            }
            CP_COMMIT();
        }
        // generate w from smem adj
#pragma unroll
        for (int k = 0; k < 16; k++) {
            int i = ig + 4 * k;
            int av = adjs[cur][i * BJ + jl];
            float x = e1s[i] + e2v;
            float w = (x > 0.f) ? As[i] * Ev : Bs[i] * Fv;
            w = (av > 0) ? w : 0.f;
            w_s[jl * WPAD + i] = w;
            den[k] += w;
        }
        __syncthreads();
        // FFMA phase
#pragma unroll 8
        for (int j = 0; j < BJ; j++) {
            ull wp[4];
#pragma unroll
            for (int p = 0; p < 4; p++)
                wp[p] = *(const ull*)&w_s[j * WPAD + 8 * tr + 2 * p];
            float4 wh4 = *(const float4*)&wh_s[j * FF + 4 * tc];
            ull d0 = f2_dup(wh4.x), d1 = f2_dup(wh4.y);
            ull d2 = f2_dup(wh4.z), d3 = f2_dup(wh4.w);
#pragma unroll
            for (int p = 0; p < 4; p++) {
                acc[p][0] = f2_fma(wp[p], d0, acc[p][0]);
                acc[p][1] = f2_fma(wp[p], d1, acc[p][1]);
                acc[p][2] = f2_fma(wp[p], d2, acc[p][2]);
                acc[p][3] = f2_fma(wp[p], d3, acc[p][3]);
            }
        }
    }

    // write numerator partials
#pragma unroll
    for (int p = 0; p < 4; p++) {
        int row = r0 + 8 * tr + 2 * p;
#pragma unroll
        for (int c = 0; c < 4; c++) {
            int col = 4 * tc + c;
            g_num[bs][row * FF + col] = f2_lo(acc[p][c]);
            g_num[bs][(row + 1) * FF + col] = f2_hi(acc[p][c]);
        }
    }
    // denominator: warp reduce over lanes (jl), lane 0 writes
#pragma unroll
    for (int k = 0; k < 16; k++) {
        float v = den[k];
#pragma unroll
        for (int o = 16; o > 0; o >>= 1) v += __shfl_xor_sync(0xffffffffu, v, o);
        if (jl == 0) g_den[bs][r0 + ig + 4 * k] = v;
    }
}

// -------------------- K5: reduce splits, normalize, ELU --------------------
__global__ __launch_bounds__(256) void k5_out(float* __restrict__ out) {
    int idx = blockIdx.x * 256 + threadIdx.x;
    int i = idx >> 6;
    float num = 0.f, den = 0.f;
#pragma unroll
    for (int s = 0; s < SPLIT; s++) num += g_num[s][idx];
#pragma unroll
    for (int s = 0; s < SPLIT; s++) den += g_den[s][i];
    den = fmaxf(den, 1e-30f);
    float v = num / den;
    out[idx] = (v > 0.f) ? v : expm1f(v);
}

// -------------------- launch --------------------
extern "C" void kernel_launch(void* const* d_in, const int* in_sizes, int n_in,
                              void* d_out, int out_size) {
    const float* h = (const float*)d_in[0];
    const int* adj = (const int*)d_in[1];
    const float* W = (const float*)d_in[2];
    const float* a = (const float*)d_in[3];
    float* out = (float*)d_out;

    k1_gemm<<<NN / 64, 256>>>(h, W);
    k2_e<<<NN / 256, 256>>>(a);
    k3_ef<<<NN / 256, 256>>>();
    k4_main<<<128 * SPLIT, TH4>>>(adj);
    k5_out<<<(NN * FF) / 256, 256>>>(out);
}

// round 3
// speedup vs baseline: 1.7647x; 1.2661x over previous
#include <cuda_runtime.h>
#include <cuda_bf16.h>
#include <cstdint>

#define NN 8192
#define FIN 512
#define FF 64
#define SPLIT 11
#define BM 128             // rows per block (K4)
#define BJ 32              // j chunk (K4)
#define TH4 128            // threads (K4)
#define WROW 158           // w_s row stride in floats (even, 158%32=30 -> ok)
#define NWRD (NN / 32)     // 256 adj words per row

typedef unsigned long long ull;

// -------------------- device scratch --------------------
__device__ float g_Wh[NN * FF];
__device__ float g_e1[NN];
__device__ float g_e2[NN];
__device__ float2 g_AB[NN];   // (A, B)
__device__ float2 g_EF[NN];   // (E, F)
__device__ float g_blockmax[32];
__device__ unsigned g_adjB[NN * NWRD];   // bit-packed adj, bit j of word [i][j/32]
__device__ float g_num[SPLIT][NN * FF];
__device__ float g_den[SPLIT][NN];

// -------------------- f32x2 helpers --------------------
__device__ __forceinline__ ull f2_fma(ull a, ull b, ull c) {
    ull d;
    asm("fma.rn.f32x2 %0, %1, %2, %3;" : "=l"(d) : "l"(a), "l"(b), "l"(c));
    return d;
}
__device__ __forceinline__ ull f2_add(ull a, ull b) {
    ull d;
    asm("add.rn.f32x2 %0, %1, %2;" : "=l"(d) : "l"(a), "l"(b));
    return d;
}
__device__ __forceinline__ ull f2_dup(float x) {
    ull d;
    asm("mov.b64 %0, {%1, %1};" : "=l"(d) : "f"(x));
    return d;
}
__device__ __forceinline__ float f2_lo(ull v) { return __uint_as_float((unsigned)v); }
__device__ __forceinline__ float f2_hi(ull v) { return __uint_as_float((unsigned)(v >> 32)); }

__device__ __forceinline__ void cp16(void* sdst, const void* gsrc) {
    unsigned s = (unsigned)__cvta_generic_to_shared(sdst);
    asm volatile("cp.async.cg.shared.global [%0], [%1], 16;\n" :: "r"(s), "l"(gsrc));
}
#define CP_COMMIT() asm volatile("cp.async.commit_group;\n" ::: "memory")
#define CP_WAIT0()  asm volatile("cp.async.wait_group 0;\n" ::: "memory")

// -------------------- K0: bit-pack adjacency --------------------
// 1024 blocks x 256 threads; warp handles one row, 256 words.
__global__ __launch_bounds__(256) void k0_pack(const int* __restrict__ adj) {
    int warp = threadIdx.x >> 5, lane = threadIdx.x & 31;
    int row = blockIdx.x * 8 + warp;
    const int* arow = adj + (size_t)row * NN;
    unsigned* brow = g_adjB + row * NWRD;
    for (int w0 = 0; w0 < NWRD; w0 += 8) {
        int v[8];
#pragma unroll
        for (int u = 0; u < 8; u++) v[u] = arow[(w0 + u) * 32 + lane];
#pragma unroll
        for (int u = 0; u < 8; u++) {
            unsigned word = __ballot_sync(0xffffffffu, v[u] > 0);
            if (lane == 0) brow[w0 + u] = word;
        }
    }
}

// -------------------- K1: Wh = h @ W --------------------
__global__ __launch_bounds__(256) void k1_gemm(const float* __restrict__ h,
                                               const float* __restrict__ W) {
    __shared__ __align__(16) float As[32 * 66];
    __shared__ __align__(16) float Bs[32 * 64];
    int t = threadIdx.x;
    int r0 = blockIdx.x * 64;
    int tx = t & 15;
    int ty = t >> 4;
    float acc[4][4];
#pragma unroll
    for (int i = 0; i < 4; i++)
#pragma unroll
        for (int j = 0; j < 4; j++) acc[i][j] = 0.f;

    for (int k0 = 0; k0 < FIN; k0 += 32) {
        __syncthreads();
#pragma unroll
        for (int q = 0; q < 8; q++) {
            int idx = t + 256 * q;
            int kk = idx & 31, i = idx >> 5;
            As[kk * 66 + i] = h[(r0 + i) * FIN + k0 + kk];
        }
#pragma unroll
        for (int q = 0; q < 8; q++) {
            int idx = t + 256 * q;
            int c = idx & 63, kk = idx >> 6;
            Bs[kk * 64 + c] = W[(k0 + kk) * FF + c];
        }
        __syncthreads();
#pragma unroll
        for (int kk = 0; kk < 32; kk++) {
            float2 a01 = *(const float2*)&As[kk * 66 + 4 * ty];
            float2 a23 = *(const float2*)&As[kk * 66 + 4 * ty + 2];
            float4 b = *(const float4*)&Bs[kk * 64 + 4 * tx];
            float av[4] = {a01.x, a01.y, a23.x, a23.y};
            float bv[4] = {b.x, b.y, b.z, b.w};
#pragma unroll
            for (int i = 0; i < 4; i++)
#pragma unroll
                for (int j = 0; j < 4; j++) acc[i][j] = fmaf(av[i], bv[j], acc[i][j]);
        }
    }
#pragma unroll
    for (int i = 0; i < 4; i++) {
        float4 v = make_float4(acc[i][0], acc[i][1], acc[i][2], acc[i][3]);
        *(float4*)&g_Wh[(r0 + 4 * ty + i) * FF + 4 * tx] = v;
    }
}

// -------------------- K2: e1, e2, per-block max(e2) --------------------
__global__ __launch_bounds__(256) void k2_e(const float* __restrict__ a) {
    __shared__ float red[256];
    int t = threadIdx.x;
    int i = blockIdx.x * 256 + t;
    const float4* wh = (const float4*)&g_Wh[i * FF];
    float e1 = 0.f, e2 = 0.f;
#pragma unroll
    for (int q = 0; q < 16; q++) {
        float4 v = wh[q];
        float4 a1 = *(const float4*)&a[q * 4];
        float4 a2 = *(const float4*)&a[FF + q * 4];
        e1 += v.x * a1.x + v.y * a1.y + v.z * a1.z + v.w * a1.w;
        e2 += v.x * a2.x + v.y * a2.y + v.z * a2.z + v.w * a2.w;
    }
    g_e1[i] = e1;
    g_e2[i] = e2;
    red[t] = e2;
    __syncthreads();
    for (int s = 128; s > 0; s >>= 1) {
        if (t < s) red[t] = fmaxf(red[t], red[t + s]);
        __syncthreads();
    }
    if (t == 0) g_blockmax[blockIdx.x] = red[0];
}

// -------------------- K3: A,B,E,F --------------------
__global__ __launch_bounds__(256) void k3_ef() {
    int i = blockIdx.x * 256 + threadIdx.x;
    float m = -1e30f;
#pragma unroll
    for (int b = 0; b < 32; b++) m = fmaxf(m, g_blockmax[b]);
    float e1 = g_e1[i], e2 = g_e2[i];
    float x = e1 + m;
    float C = (x > 0.f) ? x : 0.2f * x;   // lrelu upper bound of row max
    g_AB[i] = make_float2(expf(e1 - C), expf(0.2f * e1 - C));
    g_EF[i] = make_float2(expf(e2), expf(0.2f * e2));
}

// -------------------- K4: fused masked-attention GEMM --------------------
// grid = 64 rowblocks * SPLIT = 704 CTAs, 5/SM. Block: 128 rows x all j of its
// chunk range. Split bs covers chunks [cstart, cend): 24,24,24,23x8.
__global__ __launch_bounds__(TH4, 5) void k4_main() {
    __shared__ __align__(16) float w_s[BJ * WROW];     // [j][imap(i)]
    __shared__ __align__(16) float wh_s[BJ * FF];      // [j][f]
    __shared__ unsigned sadj[2][BM];                   // adj words, double buffered
    __shared__ float e1s[BM];
    __shared__ __align__(8) float2 ABs[BM];

    int t = threadIdx.x;
    int bi = blockIdx.x & 63;
    int bs = blockIdx.x >> 6;           // 0..10
    int r0 = bi * BM;
    int cstart = bs * 23 + ((bs < 3) ? bs : 3);
    int cend = cstart + 23 + ((bs < 3) ? 1 : 0);

    // gen mapping
    int jl = t & 31;    // j within chunk
    int ig = t >> 5;    // row group: rows ig*32 .. ig*32+31
    // ffma mapping
    int tr = t & 15;    // rows 8*tr .. 8*tr+7
    int tc = t >> 4;    // cols 8*tc .. 8*tc+7

    // prologue staging
    e1s[t] = g_e1[r0 + t];
    ABs[t] = g_AB[r0 + t];
    sadj[cstart & 1][t] = g_adjB[(r0 + t) * NWRD + cstart];
    float e2r = g_e2[cstart * BJ + jl];
    float2 efr = g_EF[cstart * BJ + jl];

    ull acc[4][8];
#pragma unroll
    for (int p = 0; p < 4; p++)
#pragma unroll
        for (int c = 0; c < 8; c++) acc[p][c] = 0ULL;
    ull accd[4] = {0ULL, 0ULL, 0ULL, 0ULL};

    for (int c = cstart; c < cend; c++) {
        int j0 = c * BJ;
        int cur = c & 1;
        float e2v = e2r;
        float2 ef = efr;

        __syncthreads();   // prev FFMA done; sadj[cur], e1s, ABs visible

        // stage Wh chunk 32x64 via cp.async (waited before next barrier)
#pragma unroll
        for (int q = 0; q < 4; q++) {
            int idx = t + TH4 * q;
            int jj = idx >> 4;
            int f4 = (idx & 15) * 4;
            cp16(&wh_s[jj * FF + f4], &g_Wh[(j0 + jj) * FF + f4]);
        }
        CP_COMMIT();

        // prefetch next chunk scalars + adj word
        unsigned aw_next = 0u;
        if (c + 1 < cend) {
            aw_next = g_adjB[(r0 + t) * NWRD + (c + 1)];
            e2r = g_e2[(c + 1) * BJ + jl];
            efr = g_EF[(c + 1) * BJ + jl];
        }

        // gen: w for rows ig*32..+31 at column j0+jl
#pragma unroll
        for (int k = 0; k < 32; k++) {
            int i = ig * 32 + k;
            unsigned aw = sadj[cur][i];
            float x = e1s[i] + e2v;
            float2 ab = ABs[i];
            float s1 = (x > 0.f) ? ab.x : ab.y;
            float s2 = (x > 0.f) ? ef.x : ef.y;
            float w = ((aw >> jl) & 1u) ? s1 * s2 : 0.f;
            w_s[jl * WROW + i + 2 * (i >> 3)] = w;
        }
        if (c + 1 < cend) sadj[cur ^ 1][t] = aw_next;

        CP_WAIT0();
        __syncthreads();   // w_s + wh_s visible

        // FFMA phase: 32 j
#pragma unroll 8
        for (int j = 0; j < BJ; j++) {
            ull wp[4];
#pragma unroll
            for (int p = 0; p < 4; p++)
                wp[p] = *(const ull*)&w_s[j * WROW + 10 * tr + 2 * p];
            float4 lo = *(const float4*)&wh_s[j * FF + 8 * tc];
            float4 hi = *(const float4*)&wh_s[j * FF + 8 * tc + 4];
            ull d[8];
            d[0] = f2_dup(lo.x); d[1] = f2_dup(lo.y);
            d[2] = f2_dup(lo.z); d[3] = f2_dup(lo.w);
            d[4] = f2_dup(hi.x); d[5] = f2_dup(hi.y);
            d[6] = f2_dup(hi.z); d[7] = f2_dup(hi.w);
#pragma unroll
            for (int p = 0; p < 4; p++) {
                accd[p] = f2_add(accd[p], wp[p]);
#pragma unroll
                for (int cc = 0; cc < 8; cc++)
                    acc[p][cc] = f2_fma(wp[p], d[cc], acc[p][cc]);
            }
        }
    }

    // write numerator partials
#pragma unroll
    for (int p = 0; p < 4; p++) {
        int row = r0 + 8 * tr + 2 * p;
#pragma unroll
        for (int cc = 0; cc < 8; cc++) {
            int col = 8 * tc + cc;
            g_num[bs][row * FF + col] = f2_lo(acc[p][cc]);
            g_num[bs][(row + 1) * FF + col] = f2_hi(acc[p][cc]);
        }
    }
    // denominator: tc==0 threads hold full sums for their 8 rows
    if (tc == 0) {
#pragma unroll
        for (int p = 0; p < 4; p++) {
            int row = r0 + 8 * tr + 2 * p;
            g_den[bs][row] = f2_lo(accd[p]);
            g_den[bs][row + 1] = f2_hi(accd[p]);
        }
    }
}

// -------------------- K5: reduce splits, normalize, ELU --------------------
__global__ __launch_bounds__(256) void k5_out(float* __restrict__ out) {
    int idx4 = blockIdx.x * 256 + threadIdx.x;   // float4 index
    int idx = idx4 * 4;
    int i = idx >> 6;
    float4 num = make_float4(0.f, 0.f, 0.f, 0.f);
    float den = 0.f;
#pragma unroll
    for (int s = 0; s < SPLIT; s++) {
        float4 v = *(const float4*)&g_num[s][idx];
        num.x += v.x; num.y += v.y; num.z += v.z; num.w += v.w;
        den += g_den[s][i];
    }
    den = fmaxf(den, 1e-30f);
    float r = 1.f / den;
    float4 o;
    o.x = num.x * r; o.y = num.y * r; o.z = num.z * r; o.w = num.w * r;
    o.x = (o.x > 0.f) ? o.x : expm1f(o.x);
    o.y = (o.y > 0.f) ? o.y : expm1f(o.y);
    o.z = (o.z > 0.f) ? o.z : expm1f(o.z);
    o.w = (o.w > 0.f) ? o.w : expm1f(o.w);
    *(float4*)&out[idx] = o;
}

// -------------------- launch --------------------
extern "C" void kernel_launch(void* const* d_in, const int* in_sizes, int n_in,
                              void* d_out, int out_size) {
    const float* h = (const float*)d_in[0];
    const int* adj = (const int*)d_in[1];
    const float* W = (const float*)d_in[2];
    const float* a = (const float*)d_in[3];
    float* out = (float*)d_out;

    k0_pack<<<NN / 8, 256>>>(adj);
    k1_gemm<<<NN / 64, 256>>>(h, W);
    k2_e<<<NN / 256, 256>>>(a);
    k3_ef<<<NN / 256, 256>>>();
    k4_main<<<64 * SPLIT, TH4>>>();
    k5_out<<<(NN * FF) / 1024, 256>>>(out);
}

// round 5
// speedup vs baseline: 2.4162x; 1.3692x over previous
#include <cuda_runtime.h>
#include <cuda_bf16.h>
#include <cstdint>

#define NN 8192
#define FIN 512
#define FF 64
#define SPLIT 4
#define BM 128
#define BJ 32
#define NWRD (NN / 32)       // 256 packed adj words per row
#define CPC (NWRD / SPLIT)   // 64 chunks per CTA
#define ASTR 40              // A_s row stride in bf16 units

typedef unsigned long long ull;

// -------------------- device scratch --------------------
__device__ float g_Wh[NN * FF];
__device__ float g_e1[NN];
__device__ float g_e2[NN];
__device__ float2 g_AB[NN];
__device__ float2 g_EF[NN];
__device__ float g_blockmax[32];
__device__ unsigned g_adjB[NN * NWRD];
__device__ unsigned g_Bh[NN * 32];   // frag-major bf16 hi of Wh^T  (1MB)
__device__ unsigned g_Bl[NN * 32];   // frag-major bf16 lo of Wh^T
__device__ float g_num[SPLIT][NN * FF];
__device__ float g_den[SPLIT][NN];

// -------------------- helpers --------------------
__device__ __forceinline__ void cp16(void* sdst, const void* gsrc) {
    unsigned s = (unsigned)__cvta_generic_to_shared(sdst);
    asm volatile("cp.async.cg.shared.global [%0], [%1], 16;\n" :: "r"(s), "l"(gsrc));
}
#define CP_COMMIT() asm volatile("cp.async.commit_group;\n" ::: "memory")
#define CP_WAIT0()  asm volatile("cp.async.wait_group 0;\n" ::: "memory")
#define CP_WAIT1()  asm volatile("cp.async.wait_group 1;\n" ::: "memory")

__device__ __forceinline__ void bf16split(float w, unsigned short& hb, unsigned short& lb) {
    __nv_bfloat16 h = __float2bfloat16(w);
    hb = *(unsigned short*)&h;
    float hf = __uint_as_float((unsigned)hb << 16);
    __nv_bfloat16 l = __float2bfloat16(w - hf);
    lb = *(unsigned short*)&l;
}

__device__ __forceinline__ void mma_bf16(float* d, unsigned a0, unsigned a1,
                                         unsigned a2, unsigned a3,
                                         unsigned b0, unsigned b1) {
    asm("mma.sync.aligned.m16n8k16.row.col.f32.bf16.bf16.f32 "
        "{%0,%1,%2,%3}, {%4,%5,%6,%7}, {%8,%9}, {%0,%1,%2,%3};"
        : "+f"(d[0]), "+f"(d[1]), "+f"(d[2]), "+f"(d[3])
        : "r"(a0), "r"(a1), "r"(a2), "r"(a3), "r"(b0), "r"(b1));
}

// -------------------- K0: bit-pack adjacency --------------------
__global__ __launch_bounds__(256) void k0_pack(const int* __restrict__ adj) {
    int warp = threadIdx.x >> 5, lane = threadIdx.x & 31;
    int row = blockIdx.x * 8 + warp;
    const int* arow = adj + (size_t)row * NN;
    unsigned* brow = g_adjB + row * NWRD;
    for (int w0 = 0; w0 < NWRD; w0 += 8) {
        int v[8];
#pragma unroll
        for (int u = 0; u < 8; u++) v[u] = arow[(w0 + u) * 32 + lane];
#pragma unroll
        for (int u = 0; u < 8; u++) {
            unsigned word = __ballot_sync(0xffffffffu, v[u] > 0);
            if (lane == 0) brow[w0 + u] = word;
        }
    }
}

// -------------------- K1: Wh = h @ W --------------------
__global__ __launch_bounds__(256) void k1_gemm(const float* __restrict__ h,
                                               const float* __restrict__ W) {
    __shared__ __align__(16) float As[32 * 66];
    __shared__ __align__(16) float Bs[32 * 64];
    int t = threadIdx.x;
    int r0 = blockIdx.x * 64;
    int tx = t & 15;
    int ty = t >> 4;
    float acc[4][4];
#pragma unroll
    for (int i = 0; i < 4; i++)
#pragma unroll
        for (int j = 0; j < 4; j++) acc[i][j] = 0.f;

    for (int k0 = 0; k0 < FIN; k0 += 32) {
        __syncthreads();
#pragma unroll
        for (int q = 0; q < 8; q++) {
            int idx = t + 256 * q;
            int kk = idx & 31, i = idx >> 5;
            As[kk * 66 + i] = h[(r0 + i) * FIN + k0 + kk];
        }
#pragma unroll
        for (int q = 0; q < 8; q++) {
            int idx = t + 256 * q;
            int c = idx & 63, kk = idx >> 6;
            Bs[kk * 64 + c] = W[(k0 + kk) * FF + c];
        }
        __syncthreads();
#pragma unroll
        for (int kk = 0; kk < 32; kk++) {
            float2 a01 = *(const float2*)&As[kk * 66 + 4 * ty];
            float2 a23 = *(const float2*)&As[kk * 66 + 4 * ty + 2];
            float4 b = *(const float4*)&Bs[kk * 64 + 4 * tx];
            float av[4] = {a01.x, a01.y, a23.x, a23.y};
            float bv[4] = {b.x, b.y, b.z, b.w};
#pragma unroll
            for (int i = 0; i < 4; i++)
#pragma unroll
                for (int j = 0; j < 4; j++) acc[i][j] = fmaf(av[i], bv[j], acc[i][j]);
        }
    }
#pragma unroll
    for (int i = 0; i < 4; i++) {
        float4 v = make_float4(acc[i][0], acc[i][1], acc[i][2], acc[i][3]);
        *(float4*)&g_Wh[(r0 + 4 * ty + i) * FF + 4 * tx] = v;
    }
}

// -------------------- K2: e1, e2, frag-major bf16 split of Wh, max --------------------
__global__ __launch_bounds__(256) void k2_e(const float* __restrict__ a) {
    __shared__ float red[256];
    int t = threadIdx.x;
    int i = blockIdx.x * 256 + t;       // global row j
    const float4* wh = (const float4*)&g_Wh[i * FF];
    unsigned short* bh16 = (unsigned short*)g_Bh;
    unsigned short* bl16 = (unsigned short*)g_Bl;

    int cch = i >> 5;
    int kk = i & 31;
    int kt = kk >> 4, k2 = kk & 15;
    int reg = k2 >> 3, half = k2 & 1, lq = (k2 & 7) >> 1;
    unsigned base = (unsigned)cch * 1024u;

    float e1 = 0.f, e2 = 0.f;
#pragma unroll
    for (int q = 0; q < 16; q++) {
        float4 v = wh[q];
        float4 a1 = *(const float4*)&a[q * 4];
        float4 a2 = *(const float4*)&a[FF + q * 4];
        e1 += v.x * a1.x + v.y * a1.y + v.z * a1.z + v.w * a1.w;
        e2 += v.x * a2.x + v.y * a2.y + v.z * a2.z + v.w * a2.w;
        float vals[4] = {v.x, v.y, v.z, v.w};
#pragma unroll
        for (int u = 0; u < 4; u++) {
            int f = q * 4 + u;
            int ft = f >> 3, n = f & 7;
            unsigned idx32 = base + (unsigned)(((kt * 8 + ft) * 32 + n * 4 + lq) * 2 + reg);
            unsigned short hb, lb;
            bf16split(vals[u], hb, lb);
            bh16[idx32 * 2 + half] = hb;
            bl16[idx32 * 2 + half] = lb;
        }
    }
    g_e1[i] = e1;
    g_e2[i] = e2;
    red[t] = e2;
    __syncthreads();
    for (int s = 128; s > 0; s >>= 1) {
        if (t < s) red[t] = fmaxf(red[t], red[t + s]);
        __syncthreads();
    }
    if (t == 0) g_blockmax[blockIdx.x] = red[0];
}

// -------------------- K3: A,B,E,F --------------------
__global__ __launch_bounds__(256) void k3_ef() {
    int i = blockIdx.x * 256 + threadIdx.x;
    float m = -1e30f;
#pragma unroll
    for (int b = 0; b < 32; b++) m = fmaxf(m, g_blockmax[b]);
    float e1 = g_e1[i], e2 = g_e2[i];
    float x = e1 + m;
    float C = (x > 0.f) ? x : 0.2f * x;
    g_AB[i] = make_float2(expf(e1 - C), expf(0.2f * e1 - C));
    g_EF[i] = make_float2(expf(e2), expf(0.2f * e2));
}

// -------------------- K4: mma.sync bf16 3-pass fused attention GEMM --------------------
// grid = 64 rowblocks * SPLIT(4) = 256 CTAs, 256 threads, 2 CTAs/SM.
// Per chunk: gen w -> split bf16 A tile; cp.async frag-major B; 48 HMMA/warp.
__global__ __launch_bounds__(256, 2) void k4_main() {
    __shared__ unsigned short Ah_s[BM * ASTR];       // 10240 B
    __shared__ unsigned short Al_s[BM * ASTR];       // 10240 B
    __shared__ __align__(16) unsigned Bh_s[2][1024]; // 8192 B
    __shared__ __align__(16) unsigned Bl_s[2][1024]; // 8192 B
    __shared__ __align__(16) float4 eabs[BM];        // (e1, A, B, -)

    int t = threadIdx.x;
    int lane = t & 31;
    int wid = t >> 5;                 // 0..7
    int bi = blockIdx.x >> 2;         // rowblock 0..63
    int bs = blockIdx.x & 3;          // split
    int r0 = bi * BM;
    int cstart = bs * CPC;
    int cend = cstart + CPC;

    // mma warp tiling: 4 m-groups x 2 n-groups
    int mw = wid & 3;                 // rows mw*32..+31
    int nw = wid >> 2;                // cols nw*32..+31

    // stage per-row scalars
    if (t < BM) {
        float2 ab = g_AB[r0 + t];
        eabs[t] = make_float4(g_e1[r0 + t], ab.x, ab.y, 0.f);
    }

    // prologue: prefetch B for first chunk
    cp16(&Bh_s[cstart & 1][t * 4], &g_Bh[cstart * 1024 + t * 4]);
    cp16(&Bl_s[cstart & 1][t * 4], &g_Bl[cstart * 1024 + t * 4]);
    CP_COMMIT();

    // adj words for first chunk (rows wid*16..+15, broadcast across lanes)
    unsigned adjw[16];
#pragma unroll
    for (int k = 0; k < 16; k++)
        adjw[k] = g_adjB[(r0 + wid * 16 + k) * NWRD + cstart];

    float acc[2][4][4];
#pragma unroll
    for (int mt = 0; mt < 2; mt++)
#pragma unroll
        for (int ft = 0; ft < 4; ft++)
#pragma unroll
            for (int u = 0; u < 4; u++) acc[mt][ft][u] = 0.f;
    float dn[16];
#pragma unroll
    for (int k = 0; k < 16; k++) dn[k] = 0.f;

    for (int c = cstart; c < cend; c++) {
        int cur = c & 1;
        int j0 = c * BJ;
        float e2v = g_e2[j0 + lane];
        float2 ef = g_EF[j0 + lane];

        __syncthreads();   // prev mma done: A_s writable, B[cur^1] reusable

        // prefetch B for chunk c+1
        if (c + 1 < cend) {
            cp16(&Bh_s[cur ^ 1][t * 4], &g_Bh[(c + 1) * 1024 + t * 4]);
            cp16(&Bl_s[cur ^ 1][t * 4], &g_Bl[(c + 1) * 1024 + t * 4]);
            CP_COMMIT();
        }

        // gen: w for 16 rows at column `lane`, split into bf16 hi/lo
#pragma unroll
        for (int k = 0; k < 16; k++) {
            int i = wid * 16 + k;
            float4 eab = eabs[i];
            float x = eab.x + e2v;
            float s1 = (x > 0.f) ? eab.y : eab.z;
            float s2 = (x > 0.f) ? ef.x : ef.y;
            float w = ((adjw[k] >> lane) & 1u) ? s1 * s2 : 0.f;
            dn[k] += w;
            unsigned short hb, lb;
            bf16split(w, hb, lb);
            Ah_s[i * ASTR + lane] = hb;
            Al_s[i * ASTR + lane] = lb;
        }
        // prefetch next adj words
        if (c + 1 < cend) {
#pragma unroll
            for (int k = 0; k < 16; k++)
                adjw[k] = g_adjB[(r0 + wid * 16 + k) * NWRD + (c + 1)];
        }

        if (c + 1 < cend) { CP_WAIT1(); } else { CP_WAIT0(); }
        __syncthreads();   // A_s + B[cur] visible to all

        // mma phase: warp computes 32x32 slice, K=32 (2 k16 tiles), 3 passes
#pragma unroll
        for (int kt = 0; kt < 2; kt++) {
            uint2 bh[4], bl[4];
#pragma unroll
            for (int ft = 0; ft < 4; ft++) {
                int ftg = nw * 4 + ft;
                int bidx = ((kt * 8 + ftg) * 32 + lane) * 2;
                bh[ft] = *(const uint2*)&Bh_s[cur][bidx];
                bl[ft] = *(const uint2*)&Bl_s[cur][bidx];
            }
#pragma unroll
            for (int mt = 0; mt < 2; mt++) {
                int r = mw * 32 + mt * 16 + (lane >> 2);
                int c0 = kt * 16 + (lane & 3) * 2;
                unsigned ah0 = *(const unsigned*)&Ah_s[r * ASTR + c0];
                unsigned ah1 = *(const unsigned*)&Ah_s[(r + 8) * ASTR + c0];
                unsigned ah2 = *(const unsigned*)&Ah_s[r * ASTR + c0 + 8];
                unsigned ah3 = *(const unsigned*)&Ah_s[(r + 8) * ASTR + c0 + 8];
                unsigned al0 = *(const unsigned*)&Al_s[r * ASTR + c0];
                unsigned al1 = *(const unsigned*)&Al_s[(r + 8) * ASTR + c0];
                unsigned al2 = *(const unsigned*)&Al_s[r * ASTR + c0 + 8];
                unsigned al3 = *(const unsigned*)&Al_s[(r + 8) * ASTR + c0 + 8];
#pragma unroll
                for (int ft = 0; ft < 4; ft++) {
                    mma_bf16(acc[mt][ft], ah0, ah1, ah2, ah3, bh[ft].x, bh[ft].y);
                    mma_bf16(acc[mt][ft], al0, al1, al2, al3, bh[ft].x, bh[ft].y);
                    mma_bf16(acc[mt][ft], ah0, ah1, ah2, ah3, bl[ft].x, bl[ft].y);
                }
            }
        }
    }

    // write numerator partials
#pragma unroll
    for (int mt = 0; mt < 2; mt++) {
        int r1 = r0 + mw * 32 + mt * 16 + (lane >> 2);
#pragma unroll
        for (int ft = 0; ft < 4; ft++) {
            int col = nw * 32 + ft * 8 + (lane & 3) * 2;
            *(float2*)&g_num[bs][r1 * FF + col] = make_float2(acc[mt][ft][0], acc[mt][ft][1]);
            *(float2*)&g_num[bs][(r1 + 8) * FF + col] = make_float2(acc[mt][ft][2], acc[mt][ft][3]);
        }
    }
    // denominator: reduce over lanes (j) for this warp's 16 gen rows
#pragma unroll
    for (int k = 0; k < 16; k++) {
        float v = dn[k];
#pragma unroll
        for (int o = 16; o > 0; o >>= 1) v += __shfl_xor_sync(0xffffffffu, v, o);
        if (lane == 0) g_den[bs][r0 + wid * 16 + k] = v;
    }
}

// -------------------- K5: reduce splits, normalize, ELU --------------------
__global__ __launch_bounds__(256) void k5_out(float* __restrict__ out) {
    int idx4 = blockIdx.x * 256 + threadIdx.x;
    int idx = idx4 * 4;
    int i = idx >> 6;
    float4 num = make_float4(0.f, 0.f, 0.f, 0.f);
    float den = 0.f;
#pragma unroll
    for (int s = 0; s < SPLIT; s++) {
        float4 v = *(const float4*)&g_num[s][idx];
        num.x += v.x; num.y += v.y; num.z += v.z; num.w += v.w;
        den += g_den[s][i];
    }
    den = fmaxf(den, 1e-30f);
    float r = 1.f / den;
    float4 o;
    o.x = num.x * r; o.y = num.y * r; o.z = num.z * r; o.w = num.w * r;
    o.x = (o.x > 0.f) ? o.x : expm1f(o.x);
    o.y = (o.y > 0.f) ? o.y : expm1f(o.y);
    o.z = (o.z > 0.f) ? o.z : expm1f(o.z);
    o.w = (o.w > 0.f) ? o.w : expm1f(o.w);
    *(float4*)&out[idx] = o;
}

// -------------------- launch --------------------
extern "C" void kernel_launch(void* const* d_in, const int* in_sizes, int n_in,
                              void* d_out, int out_size) {
    const float* h = (const float*)d_in[0];
    const int* adj = (const int*)d_in[1];
    const float* W = (const float*)d_in[2];
    const float* a = (const float*)d_in[3];
    float* out = (float*)d_out;

    k0_pack<<<NN / 8, 256>>>(adj);
    k1_gemm<<<NN / 64, 256>>>(h, W);
    k2_e<<<NN / 256, 256>>>(a);
    k3_ef<<<NN / 256, 256>>>();
    k4_main<<<64 * SPLIT, 256>>>();
    k5_out<<<(NN * FF) / 1024, 256>>>(out);
}

// round 6
// speedup vs baseline: 3.0245x; 1.2518x over previous
#include <cuda_runtime.h>
#include <cuda_bf16.h>
#include <cuda_fp16.h>
#include <cstdint>

#define NN 8192
#define FIN 512
#define FF 64
#define SPLIT 4
#define BM 128
#define BJ 32
#define NWRD (NN / 32)       // 256 packed adj words per row
#define CPC (NWRD / SPLIT)   // 64 chunks per CTA
#define ASTR 40              // A_s row stride in fp16 units (20 words: ldmatrix-perfect)

typedef unsigned long long ull;

// -------------------- device scratch --------------------
__device__ float g_Wh[NN * FF];
__device__ float g_e1[NN];
__device__ float g_e2[NN];
__device__ float2 g_AB[NN];
__device__ float2 g_EF[NN];
__device__ float g_blockmax[32];
__device__ unsigned g_adjB[NN * NWRD];
__device__ unsigned g_Bf[NN * 32];   // frag-major fp16 of Wh^T (1MB)
__device__ float g_num[SPLIT][NN * FF];
__device__ float g_den[SPLIT][NN];

// -------------------- helpers --------------------
__device__ __forceinline__ void cp16(void* sdst, const void* gsrc) {
    unsigned s = (unsigned)__cvta_generic_to_shared(sdst);
    asm volatile("cp.async.cg.shared.global [%0], [%1], 16;\n" :: "r"(s), "l"(gsrc));
}
#define CP_COMMIT() asm volatile("cp.async.commit_group;\n" ::: "memory")
#define CP_WAIT0()  asm volatile("cp.async.wait_group 0;\n" ::: "memory")
#define CP_WAIT1()  asm volatile("cp.async.wait_group 1;\n" ::: "memory")

__device__ __forceinline__ void mma_f16(float* d, unsigned a0, unsigned a1,
                                        unsigned a2, unsigned a3,
                                        unsigned b0, unsigned b1) {
    asm("mma.sync.aligned.m16n8k16.row.col.f32.f16.f16.f32 "
        "{%0,%1,%2,%3}, {%4,%5,%6,%7}, {%8,%9}, {%0,%1,%2,%3};"
        : "+f"(d[0]), "+f"(d[1]), "+f"(d[2]), "+f"(d[3])
        : "r"(a0), "r"(a1), "r"(a2), "r"(a3), "r"(b0), "r"(b1));
}

// -------------------- K0: bit-pack adjacency --------------------
__global__ __launch_bounds__(256) void k0_pack(const int* __restrict__ adj) {
    int warp = threadIdx.x >> 5, lane = threadIdx.x & 31;
    int row = blockIdx.x * 8 + warp;
    const int* arow = adj + (size_t)row * NN;
    unsigned* brow = g_adjB + row * NWRD;
    for (int w0 = 0; w0 < NWRD; w0 += 8) {
        int v[8];
#pragma unroll
        for (int u = 0; u < 8; u++) v[u] = arow[(w0 + u) * 32 + lane];
#pragma unroll
        for (int u = 0; u < 8; u++) {
            unsigned word = __ballot_sync(0xffffffffu, v[u] > 0);
            if (lane == 0) brow[w0 + u] = word;
        }
    }
}

// -------------------- K1: Wh = h @ W --------------------
__global__ __launch_bounds__(256) void k1_gemm(const float* __restrict__ h,
                                               const float* __restrict__ W) {
    __shared__ __align__(16) float As[32 * 66];
    __shared__ __align__(16) float Bs[32 * 64];
    int t = threadIdx.x;
    int r0 = blockIdx.x * 64;
    int tx = t & 15;
    int ty = t >> 4;
    float acc[4][4];
#pragma unroll
    for (int i = 0; i < 4; i++)
#pragma unroll
        for (int j = 0; j < 4; j++) acc[i][j] = 0.f;

    for (int k0 = 0; k0 < FIN; k0 += 32) {
        __syncthreads();
#pragma unroll
        for (int q = 0; q < 8; q++) {
            int idx = t + 256 * q;
            int kk = idx & 31, i = idx >> 5;
            As[kk * 66 + i] = h[(r0 + i) * FIN + k0 + kk];
        }
#pragma unroll
        for (int q = 0; q < 8; q++) {
            int idx = t + 256 * q;
            int c = idx & 63, kk = idx >> 6;
            Bs[kk * 64 + c] = W[(k0 + kk) * FF + c];
        }
        __syncthreads();
#pragma unroll
        for (int kk = 0; kk < 32; kk++) {
            float2 a01 = *(const float2*)&As[kk * 66 + 4 * ty];
            float2 a23 = *(const float2*)&As[kk * 66 + 4 * ty + 2];
            float4 b = *(const float4*)&Bs[kk * 64 + 4 * tx];
            float av[4] = {a01.x, a01.y, a23.x, a23.y};
            float bv[4] = {b.x, b.y, b.z, b.w};
#pragma unroll
            for (int i = 0; i < 4; i++)
#pragma unroll
                for (int j = 0; j < 4; j++) acc[i][j] = fmaf(av[i], bv[j], acc[i][j]);
        }
    }
#pragma unroll
    for (int i = 0; i < 4; i++) {
        float4 v = make_float4(acc[i][0], acc[i][1], acc[i][2], acc[i][3]);
        *(float4*)&g_Wh[(r0 + 4 * ty + i) * FF + 4 * tx] = v;
    }
}

// -------------------- K2: e1, e2, frag-major fp16 Wh^T, block max --------------------
__global__ __launch_bounds__(256) void k2_e(const float* __restrict__ a) {
    __shared__ float red[256];
    int t = threadIdx.x;
    int i = blockIdx.x * 256 + t;       // global row j
    const float4* wh = (const float4*)&g_Wh[i * FF];
    unsigned short* bf16p = (unsigned short*)g_Bf;

    int cch = i >> 5;
    int kk = i & 31;
    int kt = kk >> 4, k2 = kk & 15;
    int reg = k2 >> 3, half = k2 & 1, lq = (k2 & 7) >> 1;
    unsigned base = (unsigned)cch * 1024u;

    float e1 = 0.f, e2 = 0.f;
#pragma unroll
    for (int q = 0; q < 16; q++) {
        float4 v = wh[q];
        float4 a1 = *(const float4*)&a[q * 4];
        float4 a2 = *(const float4*)&a[FF + q * 4];
        e1 += v.x * a1.x + v.y * a1.y + v.z * a1.z + v.w * a1.w;
        e2 += v.x * a2.x + v.y * a2.y + v.z * a2.z + v.w * a2.w;
        float vals[4] = {v.x, v.y, v.z, v.w};
#pragma unroll
        for (int u = 0; u < 4; u++) {
            int f = q * 4 + u;
            int ft = f >> 3, n = f & 7;
            unsigned idx32 = base + (unsigned)(((kt * 8 + ft) * 32 + n * 4 + lq) * 2 + reg);
            __half hv = __float2half_rn(vals[u]);
            bf16p[idx32 * 2 + half] = *(unsigned short*)&hv;
        }
    }
    g_e1[i] = e1;
    g_e2[i] = e2;
    red[t] = e2;
    __syncthreads();
    for (int s = 128; s > 0; s >>= 1) {
        if (t < s) red[t] = fmaxf(red[t], red[t + s]);
        __syncthreads();
    }
    if (t == 0) g_blockmax[blockIdx.x] = red[0];
}

// -------------------- K3: A,B,E,F --------------------
__global__ __launch_bounds__(256) void k3_ef() {
    int i = blockIdx.x * 256 + threadIdx.x;
    float m = -1e30f;
#pragma unroll
    for (int b = 0; b < 32; b++) m = fmaxf(m, g_blockmax[b]);
    float e1 = g_e1[i], e2 = g_e2[i];
    float x = e1 + m;
    float C = (x > 0.f) ? x : 0.2f * x;
    g_AB[i] = make_float2(expf(e1 - C), expf(0.2f * e1 - C));
    g_EF[i] = make_float2(expf(e2), expf(0.2f * e2));
}

// -------------------- K4: mma.sync fp16 single-pass fused attention GEMM --------------------
// grid = 64 rowblocks * SPLIT(4) = 256 CTAs, 256 threads, 2 CTAs/SM.
__global__ __launch_bounds__(256, 2) void k4_main() {
    __shared__ unsigned short Ah_s[BM * ASTR];        // 10240 B fp16 w tile
    __shared__ __align__(16) unsigned Bf_s[2][1024];  // 8192 B fp16 frag-major B
    __shared__ __align__(16) float4 eabs[BM];         // (e1, A, B, -)

    int t = threadIdx.x;
    int lane = t & 31;
    int wid = t >> 5;                 // 0..7
    int bi = blockIdx.x >> 2;         // rowblock 0..63
    int bs = blockIdx.x & 3;          // split
    int r0 = bi * BM;
    int cstart = bs * CPC;
    int cend = cstart + CPC;

    // mma warp tiling: 4 m-groups x 2 n-groups
    int mw = wid & 3;                 // rows mw*32..+31
    int nw = wid >> 2;                // cols nw*32..+31

    // stage per-row scalars
    if (t < BM) {
        float2 ab = g_AB[r0 + t];
        eabs[t] = make_float4(g_e1[r0 + t], ab.x, ab.y, 0.f);
    }

    // ldmatrix per-lane base offset inside A tile (bytes)
    unsigned a_smem = (unsigned)__cvta_generic_to_shared(Ah_s);
    unsigned a_lane = a_smem +
        (unsigned)((((lane & 7) + ((lane >> 3) & 1) * 8) * ASTR + (lane >> 4) * 8) * 2);

    // prologue: prefetch B for first chunk
    cp16(&Bf_s[cstart & 1][t * 4], &g_Bf[cstart * 1024 + t * 4]);
    CP_COMMIT();

    // adj words for first chunk (rows wid*16..+15, broadcast across lanes)
    unsigned adjw[16];
#pragma unroll
    for (int k = 0; k < 16; k++)
        adjw[k] = g_adjB[(r0 + wid * 16 + k) * NWRD + cstart];

    float acc[2][4][4];
#pragma unroll
    for (int mt = 0; mt < 2; mt++)
#pragma unroll
        for (int ft = 0; ft < 4; ft++)
#pragma unroll
            for (int u = 0; u < 4; u++) acc[mt][ft][u] = 0.f;
    float dn[16];
#pragma unroll
    for (int k = 0; k < 16; k++) dn[k] = 0.f;

    for (int c = cstart; c < cend; c++) {
        int cur = c & 1;
        int j0 = c * BJ;
        float e2v = g_e2[j0 + lane];
        float2 ef = g_EF[j0 + lane];

        __syncthreads();   // prev mma done: A_s writable, B[cur^1] reusable

        // prefetch B for chunk c+1
        if (c + 1 < cend) {
            cp16(&Bf_s[cur ^ 1][t * 4], &g_Bf[(c + 1) * 1024 + t * 4]);
            CP_COMMIT();
        }

        // gen: w for 16 rows at column `lane`, fp16
#pragma unroll
        for (int k = 0; k < 16; k++) {
            int i = wid * 16 + k;
            float4 eab = eabs[i];
            float x = eab.x + e2v;
            float s1 = (x > 0.f) ? eab.y : eab.z;
            float s2 = (x > 0.f) ? ef.x : ef.y;
            float w = ((adjw[k] >> lane) & 1u) ? s1 * s2 : 0.f;
            dn[k] += w;
            __half hv = __float2half_rn(w);
            Ah_s[i * ASTR + lane] = *(unsigned short*)&hv;
        }
        // prefetch next adj words
        if (c + 1 < cend) {
#pragma unroll
            for (int k = 0; k < 16; k++)
                adjw[k] = g_adjB[(r0 + wid * 16 + k) * NWRD + (c + 1)];
        }

        if (c + 1 < cend) { CP_WAIT1(); } else { CP_WAIT0(); }
        __syncthreads();   // A_s + B[cur] visible to all

        // mma phase: warp computes 32x32 slice, K=32 (2 k16 tiles), single pass
#pragma unroll
        for (int kt = 0; kt < 2; kt++) {
            uint2 bfr[4];
#pragma unroll
            for (int ft = 0; ft < 4; ft++) {
                int ftg = nw * 4 + ft;
                int bidx = ((kt * 8 + ftg) * 32 + lane) * 2;
                bfr[ft] = *(const uint2*)&Bf_s[cur][bidx];
            }
#pragma unroll
            for (int mt = 0; mt < 2; mt++) {
                unsigned addr = a_lane +
                    (unsigned)(((mw * 32 + mt * 16) * ASTR + kt * 16) * 2);
                unsigned a0, a1, a2, a3;
                asm("ldmatrix.sync.aligned.m8n8.x4.shared.b16 {%0,%1,%2,%3}, [%4];"
                    : "=r"(a0), "=r"(a1), "=r"(a2), "=r"(a3) : "r"(addr));
#pragma unroll
                for (int ft = 0; ft < 4; ft++)
                    mma_f16(acc[mt][ft], a0, a1, a2, a3, bfr[ft].x, bfr[ft].y);
            }
        }
    }

    // write numerator partials
#pragma unroll
    for (int mt = 0; mt < 2; mt++) {
        int r1 = r0 + mw * 32 + mt * 16 + (lane >> 2);
#pragma unroll
        for (int ft = 0; ft < 4; ft++) {
            int col = nw * 32 + ft * 8 + (lane & 3) * 2;
            *(float2*)&g_num[bs][r1 * FF + col] = make_float2(acc[mt][ft][0], acc[mt][ft][1]);
            *(float2*)&g_num[bs][(r1 + 8) * FF + col] = make_float2(acc[mt][ft][2], acc[mt][ft][3]);
        }
    }
    // denominator: reduce over lanes (j) for this warp's 16 gen rows
#pragma unroll
    for (int k = 0; k < 16; k++) {
        float v = dn[k];
#pragma unroll
        for (int o = 16; o > 0; o >>= 1) v += __shfl_xor_sync(0xffffffffu, v, o);
        if (lane == 0) g_den[bs][r0 + wid * 16 + k] = v;
    }
}

// -------------------- K5: reduce splits, normalize, ELU --------------------
__global__ __launch_bounds__(256) void k5_out(float* __restrict__ out) {
    int idx4 = blockIdx.x * 256 + threadIdx.x;
    int idx = idx4 * 4;
    int i = idx >> 6;
    float4 num = make_float4(0.f, 0.f, 0.f, 0.f);
    float den = 0.f;
#pragma unroll
    for (int s = 0; s < SPLIT; s++) {
        float4 v = *(const float4*)&g_num[s][idx];
        num.x += v.x; num.y += v.y; num.z += v.z; num.w += v.w;
        den += g_den[s][i];
    }
    den = fmaxf(den, 1e-30f);
    float r = 1.f / den;
    float4 o;
    o.x = num.x * r; o.y = num.y * r; o.z = num.z * r; o.w = num.w * r;
    o.x = (o.x > 0.f) ? o.x : expm1f(o.x);
    o.y = (o.y > 0.f) ? o.y : expm1f(o.y);
    o.z = (o.z > 0.f) ? o.z : expm1f(o.z);
    o.w = (o.w > 0.f) ? o.w : expm1f(o.w);
    *(float4*)&out[idx] = o;
}

// -------------------- launch --------------------
extern "C" void kernel_launch(void* const* d_in, const int* in_sizes, int n_in,
                              void* d_out, int out_size) {
    const float* h = (const float*)d_in[0];
    const int* adj = (const int*)d_in[1];
    const float* W = (const float*)d_in[2];
    const float* a = (const float*)d_in[3];
    float* out = (float*)d_out;

    k0_pack<<<NN / 8, 256>>>(adj);
    k1_gemm<<<NN / 64, 256>>>(h, W);
    k2_e<<<NN / 256, 256>>>(a);
    k3_ef<<<NN / 256, 256>>>();
    k4_main<<<64 * SPLIT, 256>>>();
    k5_out<<<(NN * FF) / 1024, 256>>>(out);
}

// round 7
// speedup vs baseline: 3.3507x; 1.1079x over previous
#include <cuda_runtime.h>
#include <cuda_bf16.h>
#include <cuda_fp16.h>
#include <cstdint>

#define NN 8192
#define FIN 512
#define FF 64
#define SPLIT 4
#define BM 128
#define BJ 32
#define NCH (NN / BJ)        // 256 chunks total
#define CPC (NCH / SPLIT)    // 64 chunks per CTA
#define ASTR 40              // A_s row stride in fp16 units (20 words: ldmatrix-perfect)

typedef unsigned long long ull;

// -------------------- device scratch --------------------
__device__ float g_Wh[NN * FF];
__device__ float g_e1[NN];
__device__ float g_e2[NN];
__device__ float2 g_AB[NN];
__device__ float2 g_EF[NN];
__device__ float g_blockmax[32];
__device__ unsigned g_Bf[NN * 32];   // frag-major fp16 of Wh^T (1MB)
__device__ float g_num[SPLIT][NN * FF];
__device__ float g_den[SPLIT][NN];

// -------------------- helpers --------------------
__device__ __forceinline__ void cp16(void* sdst, const void* gsrc) {
    unsigned s = (unsigned)__cvta_generic_to_shared(sdst);
    asm volatile("cp.async.cg.shared.global [%0], [%1], 16;\n" :: "r"(s), "l"(gsrc));
}
#define CP_COMMIT() asm volatile("cp.async.commit_group;\n" ::: "memory")
#define CP_WAIT0()  asm volatile("cp.async.wait_group 0;\n" ::: "memory")
#define CP_WAIT1()  asm volatile("cp.async.wait_group 1;\n" ::: "memory")

__device__ __forceinline__ void mma_f16(float* d, unsigned a0, unsigned a1,
                                        unsigned a2, unsigned a3,
                                        unsigned b0, unsigned b1) {
    asm("mma.sync.aligned.m16n8k16.row.col.f32.f16.f16.f32 "
        "{%0,%1,%2,%3}, {%4,%5,%6,%7}, {%8,%9}, {%0,%1,%2,%3};"
        : "+f"(d[0]), "+f"(d[1]), "+f"(d[2]), "+f"(d[3])
        : "r"(a0), "r"(a1), "r"(a2), "r"(a3), "r"(b0), "r"(b1));
}

// -------------------- K1: Wh = h @ W --------------------
__global__ __launch_bounds__(256) void k1_gemm(const float* __restrict__ h,
                                               const float* __restrict__ W) {
    __shared__ __align__(16) float As[32 * 66];
    __shared__ __align__(16) float Bs[32 * 64];
    int t = threadIdx.x;
    int r0 = blockIdx.x * 64;
    int tx = t & 15;
    int ty = t >> 4;
    float acc[4][4];
#pragma unroll
    for (int i = 0; i < 4; i++)
#pragma unroll
        for (int j = 0; j < 4; j++) acc[i][j] = 0.f;

    for (int k0 = 0; k0 < FIN; k0 += 32) {
        __syncthreads();
#pragma unroll
        for (int q = 0; q < 8; q++) {
            int idx = t + 256 * q;
            int kk = idx & 31, i = idx >> 5;
            As[kk * 66 + i] = h[(r0 + i) * FIN + k0 + kk];
        }
#pragma unroll
        for (int q = 0; q < 8; q++) {
            int idx = t + 256 * q;
            int c = idx & 63, kk = idx >> 6;
            Bs[kk * 64 + c] = W[(k0 + kk) * FF + c];
        }
        __syncthreads();
#pragma unroll
        for (int kk = 0; kk < 32; kk++) {
            float2 a01 = *(const float2*)&As[kk * 66 + 4 * ty];
            float2 a23 = *(const float2*)&As[kk * 66 + 4 * ty + 2];
            float4 b = *(const float4*)&Bs[kk * 64 + 4 * tx];
            float av[4] = {a01.x, a01.y, a23.x, a23.y};
            float bv[4] = {b.x, b.y, b.z, b.w};
#pragma unroll
            for (int i = 0; i < 4; i++)
#pragma unroll
                for (int j = 0; j < 4; j++) acc[i][j] = fmaf(av[i], bv[j], acc[i][j]);
        }
    }
#pragma unroll
    for (int i = 0; i < 4; i++) {
        float4 v = make_float4(acc[i][0], acc[i][1], acc[i][2], acc[i][3]);
        *(float4*)&g_Wh[(r0 + 4 * ty + i) * FF + 4 * tx] = v;
    }
}

// -------------------- K2: e1, e2, frag-major fp16 Wh^T, block max --------------------
__global__ __launch_bounds__(256) void k2_e(const float* __restrict__ a) {
    __shared__ float red[256];
    int t = threadIdx.x;
    int i = blockIdx.x * 256 + t;       // global row j
    const float4* wh = (const float4*)&g_Wh[i * FF];
    unsigned short* bf16p = (unsigned short*)g_Bf;

    int cch = i >> 5;
    int kk = i & 31;
    int kt = kk >> 4, k2 = kk & 15;
    int reg = k2 >> 3, half = k2 & 1, lq = (k2 & 7) >> 1;
    unsigned base = (unsigned)cch * 1024u;

    float e1 = 0.f, e2 = 0.f;
#pragma unroll
    for (int q = 0; q < 16; q++) {
        float4 v = wh[q];
        float4 a1 = *(const float4*)&a[q * 4];
        float4 a2 = *(const float4*)&a[FF + q * 4];
        e1 += v.x * a1.x + v.y * a1.y + v.z * a1.z + v.w * a1.w;
        e2 += v.x * a2.x + v.y * a2.y + v.z * a2.z + v.w * a2.w;
        float vals[4] = {v.x, v.y, v.z, v.w};
#pragma unroll
        for (int u = 0; u < 4; u++) {
            int f = q * 4 + u;
            int ft = f >> 3, n = f & 7;
            unsigned idx32 = base + (unsigned)(((kt * 8 + ft) * 32 + n * 4 + lq) * 2 + reg);
            __half hv = __float2half_rn(vals[u]);
            bf16p[idx32 * 2 + half] = *(unsigned short*)&hv;
        }
    }
    g_e1[i] = e1;
    g_e2[i] = e2;
    red[t] = e2;
    __syncthreads();
    for (int s = 128; s > 0; s >>= 1) {
        if (t < s) red[t] = fmaxf(red[t], red[t + s]);
        __syncthreads();
    }
    if (t == 0) g_blockmax[blockIdx.x] = red[0];
}

// -------------------- K3: A,B,E,F --------------------
__global__ __launch_bounds__(256) void k3_ef() {
    int i = blockIdx.x * 256 + threadIdx.x;
    float m = -1e30f;
#pragma unroll
    for (int b = 0; b < 32; b++) m = fmaxf(m, g_blockmax[b]);
    float e1 = g_e1[i], e2 = g_e2[i];
    float x = e1 + m;
    float C = (x > 0.f) ? x : 0.2f * x;
    g_AB[i] = make_float2(expf(e1 - C), expf(0.2f * e1 - C));
    g_EF[i] = make_float2(expf(e2), expf(0.2f * e2));
}

// -------------------- K4: fused adj-read + fp16 mma attention GEMM --------------------
// grid = 64 rowblocks * SPLIT(4) = 256 CTAs, 256 threads, 2 CTAs/SM.
// Double-buffered A tile -> single barrier per chunk. adj read directly (no pack pass).
__global__ __launch_bounds__(256, 2) void k4_main(const int* __restrict__ adj) {
    __shared__ unsigned short Ah_s[2][BM * ASTR];     // 2 x 10240 B fp16 w tiles
    __shared__ __align__(16) unsigned Bf_s[2][1024];  // 8192 B fp16 frag-major B
    __shared__ __align__(16) float4 eabs[BM];         // (e1, A, B, -)

    int t = threadIdx.x;
    int lane = t & 31;
    int wid = t >> 5;                 // 0..7
    int bi = blockIdx.x >> 2;         // rowblock 0..63
    int bs = blockIdx.x & 3;          // split
    int r0 = bi * BM;
    int cstart = bs * CPC;
    int cend = cstart + CPC;

    // mma warp tiling: 4 m-groups x 2 n-groups
    int mw = wid & 3;                 // rows mw*32..+31
    int nw = wid >> 2;                // cols nw*32..+31

    // stage per-row scalars
    if (t < BM) {
        float2 ab = g_AB[r0 + t];
        eabs[t] = make_float4(g_e1[r0 + t], ab.x, ab.y, 0.f);
    }

    // ldmatrix per-lane base offset inside A tile (bytes), buffer 0
    unsigned a_smem = (unsigned)__cvta_generic_to_shared(&Ah_s[0][0]);
    unsigned a_lane = a_smem +
        (unsigned)((((lane & 7) + ((lane >> 3) & 1) * 8) * ASTR + (lane >> 4) * 8) * 2);

    // prologue: prefetch B, adj row-vals, e2/EF for first chunk
    cp16(&Bf_s[cstart & 1][t * 4], &g_Bf[cstart * 1024 + t * 4]);
    CP_COMMIT();

    const int* adjbase = adj + (size_t)(r0 + wid * 16) * NN + lane;
    int advj[16];
#pragma unroll
    for (int k = 0; k < 16; k++)
        advj[k] = adjbase[(size_t)k * NN + cstart * BJ];
    float e2v = g_e2[cstart * BJ + lane];
    float2 ef = g_EF[cstart * BJ + lane];

    float acc[2][4][4];
#pragma unroll
    for (int mt = 0; mt < 2; mt++)
#pragma unroll
        for (int ft = 0; ft < 4; ft++)
#pragma unroll
            for (int u = 0; u < 4; u++) acc[mt][ft][u] = 0.f;
    float dn[16];
#pragma unroll
    for (int k = 0; k < 16; k++) dn[k] = 0.f;

    __syncthreads();   // eabs visible

    for (int c = cstart; c < cend; c++) {
        int cur = c & 1;

        // gen: w for 16 rows at column `lane`, fp16, into A[cur]
#pragma unroll
        for (int k = 0; k < 16; k++) {
            int i = wid * 16 + k;
            float4 eab = eabs[i];
            float x = eab.x + e2v;
            float s1 = (x > 0.f) ? eab.y : eab.z;
            float s2 = (x > 0.f) ? ef.x : ef.y;
            float w = (advj[k] > 0) ? s1 * s2 : 0.f;
            dn[k] += w;
            __half hv = __float2half_rn(w);
            Ah_s[cur][i * ASTR + lane] = *(unsigned short*)&hv;
        }

        // prefetch next chunk: adj vals, e2/EF scalars, B tile
        if (c + 1 < cend) {
            int j1 = (c + 1) * BJ;
#pragma unroll
            for (int k = 0; k < 16; k++)
                advj[k] = adjbase[(size_t)k * NN + j1];
            e2v = g_e2[j1 + lane];
            ef = g_EF[j1 + lane];
            cp16(&Bf_s[cur ^ 1][t * 4], &g_Bf[(c + 1) * 1024 + t * 4]);
            CP_COMMIT();
            CP_WAIT1();
        } else {
            CP_WAIT0();
        }
        __syncthreads();   // A[cur] + B[cur] visible; A[cur^1] free (all mma(c-1) done)

        // mma phase: warp computes 32x32 slice, K=32 (2 k16 tiles)
#pragma unroll
        for (int kt = 0; kt < 2; kt++) {
            uint2 bfr[4];
#pragma unroll
            for (int ft = 0; ft < 4; ft++) {
                int ftg = nw * 4 + ft;
                int bidx = ((kt * 8 + ftg) * 32 + lane) * 2;
                bfr[ft] = *(const uint2*)&Bf_s[cur][bidx];
            }
#pragma unroll
            for (int mt = 0; mt < 2; mt++) {
                unsigned addr = a_lane + (unsigned)(cur * (BM * ASTR * 2)) +
                    (unsigned)(((mw * 32 + mt * 16) * ASTR + kt * 16) * 2);
                unsigned a0, a1, a2, a3;
                asm("ldmatrix.sync.aligned.m8n8.x4.shared.b16 {%0,%1,%2,%3}, [%4];"
                    : "=r"(a0), "=r"(a1), "=r"(a2), "=r"(a3) : "r"(addr));
#pragma unroll
                for (int ft = 0; ft < 4; ft++)
                    mma_f16(acc[mt][ft], a0, a1, a2, a3, bfr[ft].x, bfr[ft].y);
            }
        }
    }

    // write numerator partials
#pragma unroll
    for (int mt = 0; mt < 2; mt++) {
        int r1 = r0 + mw * 32 + mt * 16 + (lane >> 2);
#pragma unroll
        for (int ft = 0; ft < 4; ft++) {
            int col = nw * 32 + ft * 8 + (lane & 3) * 2;
            *(float2*)&g_num[bs][r1 * FF + col] = make_float2(acc[mt][ft][0], acc[mt][ft][1]);
            *(float2*)&g_num[bs][(r1 + 8) * FF + col] = make_float2(acc[mt][ft][2], acc[mt][ft][3]);
        }
    }
    // denominator: reduce over lanes (j) for this warp's 16 gen rows
#pragma unroll
    for (int k = 0; k < 16; k++) {
        float v = dn[k];
#pragma unroll
        for (int o = 16; o > 0; o >>= 1) v += __shfl_xor_sync(0xffffffffu, v, o);
        if (lane == 0) g_den[bs][r0 + wid * 16 + k] = v;
    }
}

// -------------------- K5: reduce splits, normalize, ELU --------------------
__global__ __launch_bounds__(256) void k5_out(float* __restrict__ out) {
    int idx4 = blockIdx.x * 256 + threadIdx.x;
    int idx = idx4 * 4;
    int i = idx >> 6;
    float4 num = make_float4(0.f, 0.f, 0.f, 0.f);
    float den = 0.f;
#pragma unroll
    for (int s = 0; s < SPLIT; s++) {
        float4 v = *(const float4*)&g_num[s][idx];
        num.x += v.x; num.y += v.y; num.z += v.z; num.w += v.w;
        den += g_den[s][i];
    }
    den = fmaxf(den, 1e-30f);
    float r = 1.f / den;
    float4 o;
    o.x = num.x * r; o.y = num.y * r; o.z = num.z * r; o.w = num.w * r;
    o.x = (o.x > 0.f) ? o.x : expm1f(o.x);
    o.y = (o.y > 0.f) ? o.y : expm1f(o.y);
    o.z = (o.z > 0.f) ? o.z : expm1f(o.z);
    o.w = (o.w > 0.f) ? o.w : expm1f(o.w);
    *(float4*)&out[idx] = o;
}

// -------------------- launch --------------------
extern "C" void kernel_launch(void* const* d_in, const int* in_sizes, int n_in,
                              void* d_out, int out_size) {
    const float* h = (const float*)d_in[0];
    const int* adj = (const int*)d_in[1];
    const float* W = (const float*)d_in[2];
    const float* a = (const float*)d_in[3];
    float* out = (float*)d_out;

    k1_gemm<<<NN / 64, 256>>>(h, W);
    k2_e<<<NN / 256, 256>>>(a);
    k3_ef<<<NN / 256, 256>>>();
    k4_main<<<64 * SPLIT, 256>>>(adj);
    k5_out<<<(NN * FF) / 1024, 256>>>(out);
}

// round 8
// speedup vs baseline: 4.2058x; 1.2552x over previous
#include <cuda_runtime.h>
#include <cuda_fp16.h>
#include <cstdint>

#define NN 8192
#define FIN 512
#define FF 64
#define SPLIT 5
#define BM 64
#define BJ 32
#define NCH (NN / BJ)        // 256 chunks total
#define ASTR 40              // A_s row stride in fp16 units (ldmatrix-perfect)

typedef unsigned long long ull;

// -------------------- device scratch --------------------
__device__ float g_e1[NN];
__device__ float g_e2[NN];
__device__ unsigned g_ABh[NN];       // half2 (A', B')
__device__ unsigned g_EFh[NN];       // half2 (E', F')
__device__ float g_blockmax[128];
__device__ unsigned g_Bf[NN * 32];   // frag-major fp16 of Wh^T (1MB)
__device__ float g_num[SPLIT][NN * FF];
__device__ float g_den[SPLIT][NN];

// -------------------- helpers --------------------
__device__ __forceinline__ void cp16(void* sdst, const void* gsrc) {
    unsigned s = (unsigned)__cvta_generic_to_shared(sdst);
    asm volatile("cp.async.cg.shared.global [%0], [%1], 16;\n" :: "r"(s), "l"(gsrc));
}
#define CP_COMMIT() asm volatile("cp.async.commit_group;\n" ::: "memory")
#define CP_WAIT0()  asm volatile("cp.async.wait_group 0;\n" ::: "memory")

__device__ __forceinline__ void mma_f16(float* d, unsigned a0, unsigned a1,
                                        unsigned a2, unsigned a3,
                                        unsigned b0, unsigned b1) {
    asm("mma.sync.aligned.m16n8k16.row.col.f32.f16.f16.f32 "
        "{%0,%1,%2,%3}, {%4,%5,%6,%7}, {%8,%9}, {%0,%1,%2,%3};"
        : "+f"(d[0]), "+f"(d[1]), "+f"(d[2]), "+f"(d[3])
        : "r"(a0), "r"(a1), "r"(a2), "r"(a3), "r"(b0), "r"(b1));
}

// -------------------- K1: Wh = h @ W, fused e1/e2/blockmax/fp16-frag --------------------
__global__ __launch_bounds__(256) void k1_gemm(const float* __restrict__ h,
                                               const float* __restrict__ W,
                                               const float* __restrict__ a) {
    __shared__ __align__(16) float smemU[64 * 68];  // 17408 B (As/Bs alias + WhS)
    __shared__ float red[64];
    float* As = smemU;           // 32*66 = 2112 floats
    float* Bs = smemU + 2112;    // 32*64 = 2048 floats
    int t = threadIdx.x;
    int r0 = blockIdx.x * 64;
    int tx = t & 15;
    int ty = t >> 4;
    float acc[4][4];
#pragma unroll
    for (int i = 0; i < 4; i++)
#pragma unroll
        for (int j = 0; j < 4; j++) acc[i][j] = 0.f;

    for (int k0 = 0; k0 < FIN; k0 += 32) {
        __syncthreads();
#pragma unroll
        for (int q = 0; q < 8; q++) {
            int idx = t + 256 * q;
            int kk = idx & 31, i = idx >> 5;
            As[kk * 66 + i] = h[(r0 + i) * FIN + k0 + kk];
        }
#pragma unroll
        for (int q = 0; q < 8; q++) {
            int idx = t + 256 * q;
            int c = idx & 63, kk = idx >> 6;
            Bs[kk * 64 + c] = W[(k0 + kk) * FF + c];
        }
        __syncthreads();
#pragma unroll
        for (int kk = 0; kk < 32; kk++) {
            float2 a01 = *(const float2*)&As[kk * 66 + 4 * ty];
            float2 a23 = *(const float2*)&As[kk * 66 + 4 * ty + 2];
            float4 b = *(const float4*)&Bs[kk * 64 + 4 * tx];
            float av[4] = {a01.x, a01.y, a23.x, a23.y};
            float bv[4] = {b.x, b.y, b.z, b.w};
#pragma unroll
            for (int i = 0; i < 4; i++)
#pragma unroll
                for (int j = 0; j < 4; j++) acc[i][j] = fmaf(av[i], bv[j], acc[i][j]);
        }
    }
    // ---- epilogue: Wh tile -> smem (stride 68), then e1/e2/max/fp16-frag ----
    __syncthreads();
    float* WhS = smemU;
#pragma unroll
    for (int i = 0; i < 4; i++) {
        float4 v = make_float4(acc[i][0], acc[i][1], acc[i][2], acc[i][3]);
        *(float4*)&WhS[(4 * ty + i) * 68 + 4 * tx] = v;
    }
    __syncthreads();
    if (t < 64) {
        const float4* wr = (const float4*)&WhS[t * 68];
        float e1 = 0.f, e2 = 0.f;
#pragma unroll
        for (int q = 0; q < 16; q++) {
            float4 v = wr[q];
            float4 a1 = *(const float4*)&a[q * 4];
            float4 a2 = *(const float4*)&a[FF + q * 4];
            e1 += v.x * a1.x + v.y * a1.y + v.z * a1.z + v.w * a1.w;
            e2 += v.x * a2.x + v.y * a2.y + v.z * a2.z + v.w * a2.w;
        }
        g_e1[r0 + t] = e1;
        g_e2[r0 + t] = e2;
        red[t] = e2;
    }
    __syncthreads();
    if (t < 32) {
        float m = fmaxf(red[t], red[t + 32]);
#pragma unroll
        for (int o = 16; o > 0; o >>= 1)
            m = fmaxf(m, __shfl_xor_sync(0xffffffffu, m, o));
        if (t == 0) g_blockmax[blockIdx.x] = m;
    }
    // fp16 frag-major conversion of this block's 64 Wh rows (j side)
    {
        int il = t >> 2, fq = t & 3;
        int j = r0 + il;
        int cch = j >> 5, kk = j & 31;
        int kt2 = kk >> 4, k2v = kk & 15;
        int rg = k2v >> 3, hf = k2v & 1, lq = (k2v & 7) >> 1;
        unsigned base = (unsigned)cch * 1024u;
        unsigned short* bp = (unsigned short*)g_Bf;
#pragma unroll
        for (int u = 0; u < 16; u++) {
            int f = fq * 16 + u;
            int ft = f >> 3, n = f & 7;
            unsigned idx32 = base + (unsigned)(((kt2 * 8 + ft) * 32 + n * 4 + lq) * 2 + rg);
            __half hv = __float2half_rn(WhS[il * 68 + f]);
            bp[idx32 * 2 + hf] = *(unsigned short*)&hv;
        }
    }
}

// -------------------- K3: global max, half2 A'B'/E'F' --------------------
__global__ __launch_bounds__(256) void k3_ef() {
    __shared__ float mred[128];
    int t = threadIdx.x;
    int i = blockIdx.x * 256 + t;
    if (t < 128) mred[t] = g_blockmax[t];
    __syncthreads();
    float m = -1e30f;
#pragma unroll
    for (int b = 0; b < 128; b++) m = fmaxf(m, mred[b]);
    float e1 = g_e1[i], e2 = g_e2[i];
    float x = e1 + m;
    float C = (x > 0.f) ? x : 0.2f * x;          // lrelu(e1 + M)
    float Ap = expf(x - C);                       // <= 1
    float Bp = expf(0.2f * x - C);                // <= 1
    float Ep = expf(e2 - m);                      // <= 1
    float Fp = expf(0.2f * (e2 - m));             // <= 1
    __half2 ab = __floats2half2_rn(Ap, Bp);
    __half2 ef = __floats2half2_rn(Ep, Fp);
    g_ABh[i] = *(unsigned*)&ab;
    g_EFh[i] = *(unsigned*)&ef;
}

// -------------------- K4: fused adj + fp16 mma attention GEMM --------------------
// grid = 128 rowblocks * SPLIT(5) = 640 CTAs, 128 threads, 5 CTAs/SM.
// w_ij = adj ? max(A'E', B'F') : 0 (lrelu-select == max). Den via ones B-frag.
__global__ __launch_bounds__(128, 5) void k4_main(const int* __restrict__ adj) {
    __shared__ unsigned short Ah_s[2][BM * ASTR];     // 2 x 5120 B
    __shared__ __align__(16) unsigned Bf_s[2][1024];  // 8192 B
    __shared__ unsigned abs_s[BM];                    // half2 (A',B') per row

    int t = threadIdx.x;
    int lane = t & 31;
    int wid = t >> 5;                 // 0..3
    int bi = blockIdx.x & 127;
    int bs = blockIdx.x >> 7;         // 0..4
    int r0 = bi * BM;
    int cstart = bs * 51 + (bs > 0 ? 1 : 0);
    int cend = cstart + 51 + (bs == 0 ? 1 : 0);

    int mw = wid & 1;                 // rows mw*32..+31
    int nw = wid >> 1;                // cols nw*32..+31

    if (t < BM) abs_s[t] = g_ABh[r0 + t];

    // ldmatrix per-lane base offset (bytes) in buffer 0
    unsigned a_smem = (unsigned)__cvta_generic_to_shared(&Ah_s[0][0]);
    unsigned a_lane = a_smem +
        (unsigned)((((lane & 7) + ((lane >> 3) & 1) * 8) * ASTR + (lane >> 4) * 8) * 2);
    unsigned bone = (lane < 4) ? 0x3C003C00u : 0u;   // ones-column B frag

    // prologue: B stage for first chunk
    cp16(&Bf_s[cstart & 1][t * 8], &g_Bf[cstart * 1024 + t * 8]);
    cp16(&Bf_s[cstart & 1][t * 8 + 4], &g_Bf[cstart * 1024 + t * 8 + 4]);
    CP_COMMIT();

    const int* adjbase = adj + (size_t)(r0 + wid * 16) * NN + lane;
    int advj[16];
#pragma unroll
    for (int k = 0; k < 16; k++) advj[k] = adjbase[k * NN + cstart * BJ];
    unsigned efu = g_EFh[cstart * BJ + lane];

    float acc[2][4][4];
#pragma unroll
    for (int mt = 0; mt < 2; mt++)
#pragma unroll
        for (int ft = 0; ft < 4; ft++)
#pragma unroll
            for (int u = 0; u < 4; u++) acc[mt][ft][u] = 0.f;
    float acc_d[2][4];
#pragma unroll
    for (int mt = 0; mt < 2; mt++)
#pragma unroll
        for (int u = 0; u < 4; u++) acc_d[mt][u] = 0.f;

    __syncthreads();   // abs_s visible

    for (int c = cstart; c < cend; c++) {
        int cur = c & 1;
        __half2 ef = *(__half2*)&efu;

        // gen: w for 16 rows at column `lane` into A[cur]
#pragma unroll
        for (int k = 0; k < 16; k++) {
            int i = wid * 16 + k;
            __half2 ab = *(__half2*)&abs_s[i];
            __half2 p = __hmul2(ab, ef);
            unsigned pu = *(unsigned*)&p;
            unsigned sw;
            asm("prmt.b32 %0, %1, %1, 0x1032;" : "=r"(sw) : "r"(pu));
            __half2 mx = __hmax2(*(__half2*)&pu, *(__half2*)&sw);
            unsigned short wv = (unsigned short)(*(unsigned*)&mx);
            wv = (advj[k] > 0) ? wv : (unsigned short)0;
            Ah_s[cur][i * ASTR + lane] = wv;
        }
        // prefetch next chunk's adj + ef into regs
        if (c + 1 < cend) {
            int joff = (c + 1) * BJ;
#pragma unroll
            for (int k = 0; k < 16; k++) advj[k] = adjbase[k * NN + joff];
            efu = g_EFh[joff + lane];
        }

        CP_WAIT0();        // B[cur] landed
        __syncthreads();   // A[cur] + B[cur] visible; all mma(c-1) done

        // issue next B prefetch (race-free: everyone is past mma(c-1))
        if (c + 1 < cend) {
            cp16(&Bf_s[cur ^ 1][t * 8], &g_Bf[(c + 1) * 1024 + t * 8]);
            cp16(&Bf_s[cur ^ 1][t * 8 + 4], &g_Bf[(c + 1) * 1024 + t * 8 + 4]);
            CP_COMMIT();
        }

        // mma: warp computes 32x32 slice + (nw==0) denominator column
#pragma unroll
        for (int kt = 0; kt < 2; kt++) {
            uint2 bfr[4];
#pragma unroll
            for (int ft = 0; ft < 4; ft++) {
                int ftg = nw * 4 + ft;
                bfr[ft] = *(const uint2*)&Bf_s[cur][((kt * 8 + ftg) * 32 + lane) * 2];
            }
#pragma unroll
            for (int mt = 0; mt < 2; mt++) {
                unsigned addr = a_lane + (unsigned)(cur * (BM * ASTR * 2)) +
                    (unsigned)(((mw * 32 + mt * 16) * ASTR + kt * 16) * 2);
                unsigned a0, a1, a2, a3;
                asm("ldmatrix.sync.aligned.m8n8.x4.shared.b16 {%0,%1,%2,%3}, [%4];"
                    : "=r"(a0), "=r"(a1), "=r"(a2), "=r"(a3) : "r"(addr));
#pragma unroll
                for (int ft = 0; ft < 4; ft++)
                    mma_f16(acc[mt][ft], a0, a1, a2, a3, bfr[ft].x, bfr[ft].y);
                if (nw == 0)
                    mma_f16(acc_d[mt], a0, a1, a2, a3, bone, bone);
            }
        }
    }

    // write numerator partials
#pragma unroll
    for (int mt = 0; mt < 2; mt++) {
        int r1 = r0 + mw * 32 + mt * 16 + (lane >> 2);
#pragma unroll
        for (int ft = 0; ft < 4; ft++) {
            int col = nw * 32 + ft * 8 + (lane & 3) * 2;
            *(float2*)&g_num[bs][r1 * FF + col] = make_float2(acc[mt][ft][0], acc[mt][ft][1]);
            *(float2*)&g_num[bs][(r1 + 8) * FF + col] = make_float2(acc[mt][ft][2], acc[mt][ft][3]);
        }
    }
    // denominator: ones-column lives at n-col 0 of the extra tile
    if (nw == 0 && (lane & 3) == 0) {
#pragma unroll
        for (int mt = 0; mt < 2; mt++) {
            int r1 = r0 + mw * 32 + mt * 16 + (lane >> 2);
            g_den[bs][r1] = acc_d[mt][0];
            g_den[bs][r1 + 8] = acc_d[mt][2];
        }
    }
}

// -------------------- K5: reduce splits, normalize, ELU --------------------
__global__ __launch_bounds__(256) void k5_out(float* __restrict__ out) {
    int idx4 = blockIdx.x * 256 + threadIdx.x;
    int idx = idx4 * 4;
    int i = idx >> 6;
    float4 num = make_float4(0.f, 0.f, 0.f, 0.f);
    float den = 0.f;
#pragma unroll
    for (int s = 0; s < SPLIT; s++) {
        float4 v = *(const float4*)&g_num[s][idx];
        num.x += v.x; num.y += v.y; num.z += v.z; num.w += v.w;
        den += g_den[s][i];
    }
    den = fmaxf(den, 1e-30f);
    float r = 1.f / den;
    float4 o;
    o.x = num.x * r; o.y = num.y * r; o.z = num.z * r; o.w = num.w * r;
    o.x = (o.x > 0.f) ? o.x : expm1f(o.x);
    o.y = (o.y > 0.f) ? o.y : expm1f(o.y);
    o.z = (o.z > 0.f) ? o.z : expm1f(o.z);
    o.w = (o.w > 0.f) ? o.w : expm1f(o.w);
    *(float4*)&out[idx] = o;
}

// -------------------- launch --------------------
extern "C" void kernel_launch(void* const* d_in, const int* in_sizes, int n_in,
                              void* d_out, int out_size) {
    const float* h = (const float*)d_in[0];
    const int* adj = (const int*)d_in[1];
    const float* W = (const float*)d_in[2];
    const float* a = (const float*)d_in[3];
    float* out = (float*)d_out;

    k1_gemm<<<NN / 64, 256>>>(h, W, a);
    k3_ef<<<NN / 256, 256>>>();
    k4_main<<<128 * SPLIT, 128>>>(adj);
    k5_out<<<(NN * FF) / 1024, 256>>>(out);
}

// round 10
// speedup vs baseline: 4.9335x; 1.1730x over previous
#include <cuda_runtime.h>
#include <cuda_fp16.h>
#include <cstdint>

#define NN 8192
#define FIN 512
#define FF 64
#define SPLIT 5
#define BM 64
#define BJ 32
#define NCH (NN / BJ)        // 256 chunks total
#define ASTR 40              // A_s row stride in fp16 units (ldmatrix-perfect)

typedef unsigned long long ull;

// -------------------- device scratch --------------------
__device__ float g_e1[NN];
__device__ float g_e2[NN];
__device__ unsigned g_ABh[NN];                    // half2 (A', B')
__device__ __align__(16) unsigned short g_Eh[NN]; // E' fp16
__device__ __align__(16) unsigned short g_Fh[NN]; // F' fp16
__device__ float g_blockmax[128];
__device__ unsigned g_Bf[NN * 32];                // frag-major fp16 of Wh^T (1MB)
__device__ float g_num[SPLIT][NN * FF];
__device__ float g_den[SPLIT][NN];

// -------------------- helpers --------------------
__device__ __forceinline__ void cp16(void* sdst, const void* gsrc) {
    unsigned s = (unsigned)__cvta_generic_to_shared(sdst);
    asm volatile("cp.async.cg.shared.global [%0], [%1], 16;\n" :: "r"(s), "l"(gsrc));
}
#define CP_COMMIT() asm volatile("cp.async.commit_group;\n" ::: "memory")
#define CP_WAIT0()  asm volatile("cp.async.wait_group 0;\n" ::: "memory")

__device__ __forceinline__ void mma_f16(float* d, unsigned a0, unsigned a1,
                                        unsigned a2, unsigned a3,
                                        unsigned b0, unsigned b1) {
    asm("mma.sync.aligned.m16n8k16.row.col.f32.f16.f16.f32 "
        "{%0,%1,%2,%3}, {%4,%5,%6,%7}, {%8,%9}, {%0,%1,%2,%3};"
        : "+f"(d[0]), "+f"(d[1]), "+f"(d[2]), "+f"(d[3])
        : "r"(a0), "r"(a1), "r"(a2), "r"(a3), "r"(b0), "r"(b1));
}

// -------------------- K1: Wh = h @ W, fused e1/e2/blockmax/fp16-frag --------------------
__global__ __launch_bounds__(256) void k1_gemm(const float* __restrict__ h,
                                               const float* __restrict__ W,
                                               const float* __restrict__ a) {
    __shared__ __align__(16) float smemU[64 * 68];
    __shared__ float red[64];
    float* As = smemU;
    float* Bs = smemU + 2112;
    int t = threadIdx.x;
    int r0 = blockIdx.x * 64;
    int tx = t & 15;
    int ty = t >> 4;
    float acc[4][4];
#pragma unroll
    for (int i = 0; i < 4; i++)
#pragma unroll
        for (int j = 0; j < 4; j++) acc[i][j] = 0.f;

    for (int k0 = 0; k0 < FIN; k0 += 32) {
        __syncthreads();
#pragma unroll
        for (int q = 0; q < 8; q++) {
            int idx = t + 256 * q;
            int kk = idx & 31, i = idx >> 5;
            As[kk * 66 + i] = h[(r0 + i) * FIN + k0 + kk];
        }
#pragma unroll
        for (int q = 0; q < 8; q++) {
            int idx = t + 256 * q;
            int c = idx & 63, kk = idx >> 6;
            Bs[kk * 64 + c] = W[(k0 + kk) * FF + c];
        }
        __syncthreads();
#pragma unroll
        for (int kk = 0; kk < 32; kk++) {
            float2 a01 = *(const float2*)&As[kk * 66 + 4 * ty];
            float2 a23 = *(const float2*)&As[kk * 66 + 4 * ty + 2];
            float4 b = *(const float4*)&Bs[kk * 64 + 4 * tx];
            float av[4] = {a01.x, a01.y, a23.x, a23.y};
            float bv[4] = {b.x, b.y, b.z, b.w};
#pragma unroll
            for (int i = 0; i < 4; i++)
#pragma unroll
                for (int j = 0; j < 4; j++) acc[i][j] = fmaf(av[i], bv[j], acc[i][j]);
        }
    }
    __syncthreads();
    float* WhS = smemU;
#pragma unroll
    for (int i = 0; i < 4; i++) {
        float4 v = make_float4(acc[i][0], acc[i][1], acc[i][2], acc[i][3]);
        *(float4*)&WhS[(4 * ty + i) * 68 + 4 * tx] = v;
    }
    __syncthreads();
    if (t < 64) {
        const float4* wr = (const float4*)&WhS[t * 68];
        float e1 = 0.f, e2 = 0.f;
#pragma unroll
        for (int q = 0; q < 16; q++) {
            float4 v = wr[q];
            float4 a1 = *(const float4*)&a[q * 4];
            float4 a2 = *(const float4*)&a[FF + q * 4];
            e1 += v.x * a1.x + v.y * a1.y + v.z * a1.z + v.w * a1.w;
            e2 += v.x * a2.x + v.y * a2.y + v.z * a2.z + v.w * a2.w;
        }
        g_e1[r0 + t] = e1;
        g_e2[r0 + t] = e2;
        red[t] = e2;
    }
    __syncthreads();
    if (t < 32) {
        float m = fmaxf(red[t], red[t + 32]);
#pragma unroll
        for (int o = 16; o > 0; o >>= 1)
            m = fmaxf(m, __shfl_xor_sync(0xffffffffu, m, o));
        if (t == 0) g_blockmax[blockIdx.x] = m;
    }
    // fp16 frag-major conversion of this block's 64 Wh rows (j side)
    {
        int il = t >> 2, fq = t & 3;
        int j = r0 + il;
        int cch = j >> 5, kk = j & 31;
        int kt2 = kk >> 4, k2v = kk & 15;
        int rg = k2v >> 3, hf = k2v & 1, lq = (k2v & 7) >> 1;
        unsigned base = (unsigned)cch * 1024u;
        unsigned short* bp = (unsigned short*)g_Bf;
#pragma unroll
        for (int u = 0; u < 16; u++) {
            int f = fq * 16 + u;
            int ft = f >> 3, n = f & 7;
            unsigned idx32 = base + (unsigned)(((kt2 * 8 + ft) * 32 + n * 4 + lq) * 2 + rg);
            __half hv = __float2half_rn(WhS[il * 68 + f]);
            bp[idx32 * 2 + hf] = *(unsigned short*)&hv;
        }
    }
}

// -------------------- K3: global max, A'B' half2, E'/F' half arrays --------------------
__global__ __launch_bounds__(256) void k3_ef() {
    __shared__ float mred[128];
    int t = threadIdx.x;
    int i = blockIdx.x * 256 + t;
    if (t < 128) mred[t] = g_blockmax[t];
    __syncthreads();
    float m = -1e30f;
#pragma unroll
    for (int b = 0; b < 128; b++) m = fmaxf(m, mred[b]);
    float e1 = g_e1[i], e2 = g_e2[i];
    float x = e1 + m;
    float C = (x > 0.f) ? x : 0.2f * x;          // lrelu(e1 + M)
    float Ap = expf(x - C);
    float Bp = expf(0.2f * x - C);
    float Ep = expf(e2 - m);
    float Fp = expf(0.2f * (e2 - m));
    __half2 ab = __floats2half2_rn(Ap, Bp);
    g_ABh[i] = *(unsigned*)&ab;
    __half eh = __float2half_rn(Ep), fh = __float2half_rn(Fp);
    g_Eh[i] = *(unsigned short*)&eh;
    g_Fh[i] = *(unsigned short*)&fh;
}

// -------------------- K4: fused adj + fp16 mma attention GEMM --------------------
// grid = 128 rowblocks * SPLIT(5) = 640 CTAs, 128 threads, 5 CTAs/SM.
// Gen: thread <-> (row, j-half). adj in {0,1} -> mask by half2 multiply.
__global__ __launch_bounds__(128, 5) void k4_main(const int* __restrict__ adj) {
    __shared__ unsigned short Ah_s[2][BM * ASTR];     // 2 x 5120 B
    __shared__ __align__(16) unsigned Bf_s[2][1024];  // 8192 B

    int t = threadIdx.x;
    int lane = t & 31;
    int wid = t >> 5;                 // 0..3
    int bi = blockIdx.x & 127;
    int bs = blockIdx.x >> 7;         // 0..4
    int r0 = bi * BM;
    int cstart = bs * 51 + (bs > 0 ? 1 : 0);
    int cend = cstart + 51 + (bs == 0 ? 1 : 0);

    int mw = wid & 1;                 // mma rows mw*32..+31
    int nw = wid >> 1;                // mma cols nw*32..+31

    // gen mapping: thread -> (row, half)
    int row = t >> 1;
    int jh = t & 1;

    // row-constant scalars
    unsigned abu = g_ABh[r0 + row];
    __half2 abh = *(__half2*)&abu;
    __half2 aa = __half2half2(__low2half(abh));
    __half2 bb = __half2half2(__high2half(abh));

    // pointers
    const uint4* adjp = (const uint4*)(adj + (size_t)(r0 + row) * NN + 16 * jh);
    const uint4* epE = (const uint4*)g_Eh;
    const uint4* epF = (const uint4*)g_Fh;

    // ldmatrix per-lane base offset (bytes) in buffer 0
    unsigned a_smem = (unsigned)__cvta_generic_to_shared(&Ah_s[0][0]);
    unsigned a_lane = a_smem +
        (unsigned)((((lane & 7) + ((lane >> 3) & 1) * 8) * ASTR + (lane >> 4) * 8) * 2);

    // prologue: B stage + adj/E/F regs for first chunk
    cp16(&Bf_s[cstart & 1][t * 8], &g_Bf[cstart * 1024 + t * 8]);
    cp16(&Bf_s[cstart & 1][t * 8 + 4], &g_Bf[cstart * 1024 + t * 8 + 4]);
    CP_COMMIT();

    uint4 av[4], ev[2], fv[2];
#pragma unroll
    for (int q = 0; q < 4; q++) av[q] = adjp[(size_t)cstart * 8 + q];
#pragma unroll
    for (int r = 0; r < 2; r++) {
        ev[r] = epE[cstart * 4 + 2 * jh + r];
        fv[r] = epF[cstart * 4 + 2 * jh + r];
    }

    float acc[2][4][4];
#pragma unroll
    for (int mt = 0; mt < 2; mt++)
#pragma unroll
        for (int ft = 0; ft < 4; ft++)
#pragma unroll
            for (int u = 0; u < 4; u++) acc[mt][ft][u] = 0.f;
    float dnf = 0.f;

    for (int c = cstart; c < cend; c++) {
        int cur = c & 1;

        // gen: 16 w values for (row, j0+16*jh .. +15)
        unsigned wv[8];
        __half2 dn2 = __float2half2_rn(0.f);
#pragma unroll
        for (int p = 0; p < 8; p++) {
            unsigned eu = ((const unsigned*)ev)[p];
            unsigned fu = ((const unsigned*)fv)[p];
            __half2 w2 = __hmul2(aa, *(__half2*)&eu);
            __half2 v2 = __hmul2(bb, *(__half2*)&fu);
            w2 = __hmax2(w2, v2);
            unsigned a0 = ((const unsigned*)av)[2 * p];
            unsigned a1 = ((const unsigned*)av)[2 * p + 1];
            unsigned msk = a0 * 0x3C00u + a1 * 0x3C000000u;
            w2 = __hmul2(w2, *(__half2*)&msk);
            dn2 = __hadd2(dn2, w2);
            wv[p] = *(unsigned*)&w2;
        }
        *(uint4*)&Ah_s[cur][row * ASTR + 16 * jh] =
            make_uint4(wv[0], wv[1], wv[2], wv[3]);
        *(uint4*)&Ah_s[cur][row * ASTR + 16 * jh + 8] =
            make_uint4(wv[4], wv[5], wv[6], wv[7]);
        float2 df = __half22float2(dn2);
        dnf += df.x + df.y;

        // prefetch next chunk's adj/E/F
        if (c + 1 < cend) {
#pragma unroll
            for (int q = 0; q < 4; q++) av[q] = adjp[(size_t)(c + 1) * 8 + q];
#pragma unroll
            for (int r = 0; r < 2; r++) {
                ev[r] = epE[(c + 1) * 4 + 2 * jh + r];
                fv[r] = epF[(c + 1) * 4 + 2 * jh + r];
            }
        }

        CP_WAIT0();        // B[cur] landed
        __syncthreads();   // A[cur] + B[cur] visible; all mma(c-1) done

        // issue next B prefetch (race-free: everyone past mma(c-1))
        if (c + 1 < cend) {
            cp16(&Bf_s[cur ^ 1][t * 8], &g_Bf[(c + 1) * 1024 + t * 8]);
            cp16(&Bf_s[cur ^ 1][t * 8 + 4], &g_Bf[(c + 1) * 1024 + t * 8 + 4]);
            CP_COMMIT();
        }

        // mma: warp computes 32x32 slice
#pragma unroll
        for (int kt = 0; kt < 2; kt++) {
            uint2 bfr[4];
#pragma unroll
            for (int ft = 0; ft < 4; ft++) {
                int ftg = nw * 4 + ft;
                bfr[ft] = *(const uint2*)&Bf_s[cur][((kt * 8 + ftg) * 32 + lane) * 2];
            }
#pragma unroll
            for (int mt = 0; mt < 2; mt++) {
                unsigned addr = a_lane + (unsigned)(cur * (BM * ASTR * 2)) +
                    (unsigned)(((mw * 32 + mt * 16) * ASTR + kt * 16) * 2);
                unsigned a0, a1, a2, a3;
                asm("ldmatrix.sync.aligned.m8n8.x4.shared.b16 {%0,%1,%2,%3}, [%4];"
                    : "=r"(a0), "=r"(a1), "=r"(a2), "=r"(a3) : "r"(addr));
#pragma unroll
                for (int ft = 0; ft < 4; ft++)
                    mma_f16(acc[mt][ft], a0, a1, a2, a3, bfr[ft].x, bfr[ft].y);
            }
        }
    }

    // write numerator partials
#pragma unroll
    for (int mt = 0; mt < 2; mt++) {
        int r1 = r0 + mw * 32 + mt * 16 + (lane >> 2);
#pragma unroll
        for (int ft = 0; ft < 4; ft++) {
            int col = nw * 32 + ft * 8 + (lane & 3) * 2;
            *(float2*)&g_num[bs][r1 * FF + col] = make_float2(acc[mt][ft][0], acc[mt][ft][1]);
            *(float2*)&g_num[bs][(r1 + 8) * FF + col] = make_float2(acc[mt][ft][2], acc[mt][ft][3]);
        }
    }
    // denominator: combine the two j-halves of each row
    float dn = dnf + __shfl_xor_sync(0xffffffffu, dnf, 1);
    if (jh == 0) g_den[bs][r0 + row] = dn;
}

// -------------------- K5: reduce splits, normalize, ELU --------------------
__global__ __launch_bounds__(256) void k5_out(float* __restrict__ out) {
    int idx4 = blockIdx.x * 256 + threadIdx.x;
    int idx = idx4 * 4;
    int i = idx >> 6;
    float4 num = make_float4(0.f, 0.f, 0.f, 0.f);
    float den = 0.f;
#pragma unroll
    for (int s = 0; s < SPLIT; s++) {
        float4 v = *(const float4*)&g_num[s][idx];
        num.x += v.x; num.y += v.y; num.z += v.z; num.w += v.w;
        den += g_den[s][i];
    }
    den = fmaxf(den, 1e-30f);
    float r = 1.f / den;
    float4 o;
    o.x = num.x * r; o.y = num.y * r; o.z = num.z * r; o.w = num.w * r;
    o.x = (o.x > 0.f) ? o.x : expm1f(o.x);
    o.y = (o.y > 0.f) ? o.y : expm1f(o.y);
    o.z = (o.z > 0.f) ? o.z : expm1f(o.z);
    o.w = (o.w > 0.f) ? o.w : expm1f(o.w);
    *(float4*)&out[idx] = o;
}

// -------------------- launch --------------------
extern "C" void kernel_launch(void* const* d_in, const int* in_sizes, int n_in,
                              void* d_out, int out_size) {
    const float* h = (const float*)d_in[0];
    const int* adj = (const int*)d_in[1];
    const float* W = (const float*)d_in[2];
    const float* a = (const float*)d_in[3];
    float* out = (float*)d_out;

    k1_gemm<<<NN / 64, 256>>>(h, W, a);
    k3_ef<<<NN / 256, 256>>>();
    k4_main<<<128 * SPLIT, 128>>>(adj);
    k5_out<<<(NN * FF) / 1024, 256>>>(out);
}